// round 9
// baseline (speedup 1.0000x reference)
#include <cuda_runtime.h>
#include <cuda_bf16.h>
#include <cstdint>
#include <cstddef>

#define BATCH 1024
#define HW 1024   // 32*32

// ---------------- scratch (device globals; no allocs allowed) ----------------
__device__ __nv_bfloat16 g_Hhi[(size_t)BATCH * HW * 64];  // 128 MB each
__device__ __nv_bfloat16 g_Hlo[(size_t)BATCH * HW * 64];
__device__ __nv_bfloat16 g_Rhi[(size_t)BATCH * HW * 64];
__device__ __nv_bfloat16 g_Rlo[(size_t)BATCH * HW * 64];
__device__ __nv_bfloat16 g_Whi[4 * 9 * 64 * 72];
__device__ __nv_bfloat16 g_Wlo[4 * 9 * 64 * 72];
__device__ float g_gap[BATCH * 64];
__device__ int   g_flag[BATCH];

// ---------------- misc ----------------
__global__ void zero_conf(float* conf) {
    int t = threadIdx.x;
    if (t < 100) conf[t] = 0.0f;
}

// weight prep: OIHW fp32 [64][64][3][3] -> [s=9][co=64][ci pad 72] bf16 hi/lo
__global__ void prep_w(const float* __restrict__ w, __nv_bfloat16* __restrict__ whi,
                       __nv_bfloat16* __restrict__ wlo) {
    int idx = blockIdx.x * 256 + threadIdx.x;          // 9*64*72 = 41472
    if (idx >= 9 * 64 * 72) return;
    int s = idx / (64 * 72), rem = idx % (64 * 72), co = rem / 72, ci = rem % 72;
    float v = 0.0f;
    if (ci < 64) v = w[(co * 64 + ci) * 9 + s];
    __nv_bfloat16 h = __float2bfloat16(v);
    whi[idx] = h;
    wlo[idx] = __float2bfloat16(v - __bfloat162float(h));
}

// ---------------- fused LeNet: conv1+pool, conv2+pool, FCs, argmax/softmax/conf ----------------
__global__ __launch_bounds__(256) void lenet_all(
        const float* __restrict__ x, const float* __restrict__ w1, const float* __restrict__ b1,
        const float* __restrict__ w2, const float* __restrict__ b2,
        const float* __restrict__ fc1w, const float* __restrict__ fc1b,
        const float* __restrict__ fc2w, const float* __restrict__ fc2b,
        const float* __restrict__ fc3w, const float* __restrict__ fc3b,
        const float* __restrict__ thr_p, const int* __restrict__ labels,
        float* __restrict__ lenout, float* conf, int* __restrict__ flag) {
    __shared__ float sx[3 * 32 * 32];
    __shared__ float sw[2400];
    __shared__ float p1[1176];
    __shared__ float p2[400];
    __shared__ float h1[120];
    __shared__ float h2[84];
    __shared__ float lg[10];
    __shared__ float sb[16];
    int bid = blockIdx.x, t = threadIdx.x;
    const float* xb = x + (size_t)bid * 3072;
    for (int i = t; i < 3072; i += 256) sx[i] = xb[i];
    for (int i = t; i < 450; i += 256) sw[i] = w1[i];
    if (t < 6) sb[t] = b1[t];
    __syncthreads();
    for (int idx = t; idx < 6 * 14 * 14; idx += 256) {
        int c = idx / 196, py = (idx / 14) % 14, px = idx % 14;
        float m = -1e30f;
        #pragma unroll
        for (int dy = 0; dy < 2; dy++)
            #pragma unroll
            for (int dx = 0; dx < 2; dx++) {
                int y = 2 * py + dy, x0 = 2 * px + dx;
                float a = sb[c];
                for (int ci = 0; ci < 3; ci++)
                    #pragma unroll
                    for (int ky = 0; ky < 5; ky++)
                        #pragma unroll
                        for (int kx = 0; kx < 5; kx++)
                            a = fmaf(sx[ci * 1024 + (y + ky) * 32 + (x0 + kx)],
                                     sw[(c * 3 + ci) * 25 + ky * 5 + kx], a);
                m = fmaxf(m, a);
            }
        p1[idx] = fmaxf(m, 0.0f);
    }
    __syncthreads();
    for (int i = t; i < 2400; i += 256) sw[i] = w2[i];
    if (t < 16) sb[t] = b2[t];
    __syncthreads();
    for (int idx = t; idx < 400; idx += 256) {
        int c = idx / 25, py = (idx / 5) % 5, px = idx % 5;
        float m = -1e30f;
        #pragma unroll
        for (int dy = 0; dy < 2; dy++)
            #pragma unroll
            for (int dx = 0; dx < 2; dx++) {
                int y = 2 * py + dy, x0 = 2 * px + dx;
                float a = sb[c];
                for (int ci = 0; ci < 6; ci++)
                    #pragma unroll
                    for (int ky = 0; ky < 5; ky++)
                        #pragma unroll
                        for (int kx = 0; kx < 5; kx++)
                            a = fmaf(p1[ci * 196 + (y + ky) * 14 + (x0 + kx)],
                                     sw[(c * 6 + ci) * 25 + ky * 5 + kx], a);
                m = fmaxf(m, a);
            }
        p2[idx] = fmaxf(m, 0.0f);
    }
    __syncthreads();
    if (t < 120) {
        float a = fc1b[t];
        for (int k = 0; k < 400; k++) a = fmaf(p2[k], fc1w[k * 120 + t], a);
        h1[t] = fmaxf(a, 0.0f);
    }
    __syncthreads();
    if (t < 84) {
        float a = fc2b[t];
        for (int k = 0; k < 120; k++) a = fmaf(h1[k], fc2w[k * 84 + t], a);
        h2[t] = fmaxf(a, 0.0f);
    }
    __syncthreads();
    if (t < 10) {
        float a = fc3b[t];
        for (int k = 0; k < 84; k++) a = fmaf(h2[k], fc3w[k * 10 + t], a);
        lg[t] = a;
        lenout[(size_t)bid * 10 + t] = a;
    }
    __syncthreads();
    if (t == 0) {
        float m = lg[0]; int am = 0;
        #pragma unroll
        for (int i = 1; i < 10; i++) if (lg[i] > m) { m = lg[i]; am = i; }
        float p[10]; float s = 0.0f;
        #pragma unroll
        for (int i = 0; i < 10; i++) { p[i] = expf(lg[i] - m); s += p[i]; }
        float inv = 1.0f / s;
        float p0 = -1.0f, pp1 = -1.0f;
        #pragma unroll
        for (int i = 0; i < 10; i++) {
            float v = p[i] * inv;
            if (v > p0) { pp1 = p0; p0 = v; } else if (v > pp1) { pp1 = v; }
        }
        flag[bid] = ((p0 - pp1) <= thr_p[0]) ? 1 : 0;
        atomicAdd(&conf[labels[bid] * 10 + am], 1.0f);
    }
}

// ---------------- split helper ----------------
__device__ __forceinline__ void split_bf16(float v, __nv_bfloat16& h, __nv_bfloat16& l) {
    h = __float2bfloat16(v);
    l = __float2bfloat16(v - __bfloat162float(h));
}

// ---------------- ResNet conv0 (3->64, fp32 direct), hi/lo NHWC out + ReLU ----------------
__global__ __launch_bounds__(256, 2) void conv0_k(const float* __restrict__ x,
        const float* __restrict__ w, const float* __restrict__ bias,
        __nv_bfloat16* __restrict__ ohi, __nv_bfloat16* __restrict__ olo) {
    __shared__ __align__(16) float s_in[3 * 10 * 36];
    __shared__ float s_w[3 * 64 * 9];
    int b = blockIdx.x, row0 = blockIdx.y * 8;
    int t = threadIdx.x, warp = t >> 5, lane = t & 31;
    int r2 = lane >> 3, colg = lane & 7, cob = warp * 8;

    float acc[2][4][8];
    #pragma unroll
    for (int oc = 0; oc < 8; oc++) {
        float bv = bias[cob + oc];
        #pragma unroll
        for (int rr = 0; rr < 2; rr++)
            #pragma unroll
            for (int cc = 0; cc < 4; cc++) acc[rr][cc][oc] = bv;
    }
    const float* inb = x + (size_t)b * 3 * HW;
    for (int idx = t; idx < 3 * 340; idx += 256) {
        int kc = idx / 340, rem = idx % 340, r = rem / 34, c = rem % 34;
        int gr = row0 - 1 + r, gc = c - 1;
        float v = 0.0f;
        if ((unsigned)gr < 32u && (unsigned)gc < 32u)
            v = inb[(size_t)kc * HW + gr * 32 + gc];
        s_in[kc * 360 + r * 36 + c] = v;
    }
    for (int idx = t; idx < 3 * 576; idx += 256) {
        int kc = idx / 576, rem = idx % 576, co = rem / 9, k = rem % 9;
        s_w[idx] = w[((size_t)co * 3 + kc) * 9 + k];
    }
    __syncthreads();
    #pragma unroll
    for (int kc = 0; kc < 3; kc++) {
        float xin[4][6];
        const float* sbase = s_in + kc * 360 + (r2 * 2) * 36 + colg * 4;
        #pragma unroll
        for (int r = 0; r < 4; r++) {
            float4 a = *reinterpret_cast<const float4*>(sbase + r * 36);
            float2 bv = *reinterpret_cast<const float2*>(sbase + r * 36 + 4);
            xin[r][0] = a.x; xin[r][1] = a.y; xin[r][2] = a.z; xin[r][3] = a.w;
            xin[r][4] = bv.x; xin[r][5] = bv.y;
        }
        const float* wp = s_w + kc * 576 + cob * 9;
        #pragma unroll
        for (int oc = 0; oc < 8; oc++) {
            float w0 = wp[oc * 9], w1 = wp[oc * 9 + 1], w2 = wp[oc * 9 + 2];
            float w3 = wp[oc * 9 + 3], w4 = wp[oc * 9 + 4], w5 = wp[oc * 9 + 5];
            float w6 = wp[oc * 9 + 6], w7 = wp[oc * 9 + 7], w8 = wp[oc * 9 + 8];
            #pragma unroll
            for (int rr = 0; rr < 2; rr++)
                #pragma unroll
                for (int cc = 0; cc < 4; cc++) {
                    float a = acc[rr][cc][oc];
                    a = fmaf(xin[rr][cc],     w0, a);
                    a = fmaf(xin[rr][cc + 1], w1, a);
                    a = fmaf(xin[rr][cc + 2], w2, a);
                    a = fmaf(xin[rr + 1][cc],     w3, a);
                    a = fmaf(xin[rr + 1][cc + 1], w4, a);
                    a = fmaf(xin[rr + 1][cc + 2], w5, a);
                    a = fmaf(xin[rr + 2][cc],     w6, a);
                    a = fmaf(xin[rr + 2][cc + 1], w7, a);
                    a = fmaf(xin[rr + 2][cc + 2], w8, a);
                    acc[rr][cc][oc] = a;
                }
        }
    }
    size_t ob = (size_t)b * HW * 64;
    #pragma unroll
    for (int rr = 0; rr < 2; rr++)
        #pragma unroll
        for (int cc = 0; cc < 4; cc++) {
            int px = (row0 + r2 * 2 + rr) * 32 + colg * 4 + cc;
            __nv_bfloat16 hv[8], lv[8];
            #pragma unroll
            for (int oc = 0; oc < 8; oc++)
                split_bf16(fmaxf(acc[rr][cc][oc], 0.f), hv[oc], lv[oc]);
            *reinterpret_cast<uint4*>(ohi + ob + (size_t)px * 64 + cob) =
                *reinterpret_cast<uint4*>(hv);
            *reinterpret_cast<uint4*>(olo + ob + (size_t)px * 64 + cob) =
                *reinterpret_cast<uint4*>(lv);
        }
}

// ---------------- bf16x3 tensor-core 3x3 SAME conv, 64->64, hi/lo NHWC ----------------
__device__ __forceinline__ void mma_bf16(float* d, uint32_t a0, uint32_t a1, uint32_t a2,
                                         uint32_t a3, uint32_t b0, uint32_t b1) {
    asm volatile("mma.sync.aligned.m16n8k16.row.col.f32.bf16.bf16.f32 "
                 "{%0,%1,%2,%3}, {%4,%5,%6,%7}, {%8,%9}, {%0,%1,%2,%3};"
                 : "+f"(d[0]), "+f"(d[1]), "+f"(d[2]), "+f"(d[3])
                 : "r"(a0), "r"(a1), "r"(a2), "r"(a3), "r"(b0), "r"(b1));
}

#define IN_PITCH 36                 // words per px row (64 ci bf16 data + pad)
#define PLANE    7344               // 204 px (6 rows x 34 cols) * 36 words
#define WOFF     14688              // W buffers start (words)
#define WPLANE   2304               // 64 co * 36 words
#define SMEM_WORDS (WOFF + 2 * 2 * WPLANE)          // 23904
#define SMEM_BYTES (SMEM_WORDS * 4)                 // 95616

// Warp tiling: 8 warps = 4 px-groups (32 px) x 2 co-groups (32 co).
// Per warp: 2 m16 co-tiles x 4 n8 px-tiles. Balanced 32x32 minimizes smem bytes.
__global__ __launch_bounds__(256, 2) void conv_mma(
        const __nv_bfloat16* __restrict__ inhi,   // [B][1024][64]
        const __nv_bfloat16* __restrict__ inlo,
        const __nv_bfloat16* __restrict__ whi,    // [9][64][72]
        const __nv_bfloat16* __restrict__ wlo,
        const float* __restrict__ bias,
        const __nv_bfloat16* reshi, const __nv_bfloat16* reslo,
        __nv_bfloat16* __restrict__ outhi, __nv_bfloat16* __restrict__ outlo) {
    extern __shared__ uint32_t sm[];
    int b = blockIdx.x, g = blockIdx.y, r0 = g * 4;
    int t = threadIdx.x, lane = t & 31, warp = t >> 5;
    int cobase = (warp >> 2) * 32;           // 2 co-groups of 32
    int pxbase = (warp & 3) * 32;            // 4 px-groups of 32

    // ---- stage input tile via cp.async: 6 rows x 34 cols, hi+lo planes ----
    const __nv_bfloat16* hbase = inhi + (size_t)b * HW * 64;
    const __nv_bfloat16* lbase = inlo + (size_t)b * HW * 64;
    for (int idx = t; idx < 3264; idx += 256) {          // 2 planes * 204 px * 8 chunks
        int plane = idx >= 1632;
        int rem = idx - plane * 1632;
        int pxt = rem >> 3, ck = rem & 7;
        int rt = pxt / 34, ct = pxt % 34;
        int gr = r0 - 1 + rt, gc = ct - 1;
        int ok = ((unsigned)gr < 32u) && ((unsigned)gc < 32u);
        const __nv_bfloat16* base = plane ? lbase : hbase;
        const char* src = reinterpret_cast<const char*>(
            base + (ok ? ((size_t)(gr * 32 + gc)) * 64 + ck * 8 : 0));
        uint32_t dst = (uint32_t)__cvta_generic_to_shared(
            sm + plane * PLANE + pxt * IN_PITCH + ck * 4);
        int sz = ok ? 16 : 0;
        asm volatile("cp.async.ca.shared.global [%0], [%1], 16, %2;"
                     :: "r"(dst), "l"(src), "r"(sz));
    }

    // ---- cp.async weight staging, per shift, double buffered ----
    auto issueW = [&](int s, int buf) {
        for (int c = t; c < 1152; c += 256) {            // 2 planes * 576 16B chunks
            int plane = (c >= 576) ? 1 : 0;
            int cc = c - plane * 576;
            const char* src = reinterpret_cast<const char*>(plane ? wlo : whi)
                              + (size_t)s * 9216 + cc * 16;
            uint32_t dst = (uint32_t)__cvta_generic_to_shared(
                sm + WOFF + buf * (2 * WPLANE) + plane * WPLANE + cc * 4);
            asm volatile("cp.async.ca.shared.global [%0], [%1], 16;" :: "r"(dst), "l"(src));
        }
        asm volatile("cp.async.commit_group;" ::: "memory");
    };
    issueW(0, 0);

    // ---- accumulators + per-thread base offsets ----
    float acc[2][4][4];
    #pragma unroll
    for (int mt = 0; mt < 2; mt++) {
        float bv0 = bias[cobase + mt * 16 + (lane >> 2)];
        float bv1 = bias[cobase + mt * 16 + (lane >> 2) + 8];
        #pragma unroll
        for (int j = 0; j < 4; j++) {
            acc[mt][j][0] = bv0; acc[mt][j][1] = bv0;
            acc[mt][j][2] = bv1; acc[mt][j][3] = bv1;
        }
    }
    int bword[4];
    #pragma unroll
    for (int j = 0; j < 4; j++) {
        int p = pxbase + j * 8 + (lane >> 2);
        int r = p >> 5, c = p & 31;
        bword[j] = (r * 34 + c) * IN_PITCH + (lane & 3);
    }
    int awbase = (cobase + (lane >> 2)) * IN_PITCH + (lane & 3);

    // ---- main loop over 9 shifts ----
    for (int s = 0; s < 9; s++) {
        int buf = s & 1;
        asm volatile("cp.async.wait_group 0;" ::: "memory");
        __syncthreads();
        if (s < 8) issueW(s + 1, buf ^ 1);
        int ky = s / 3, kx = s - 3 * ky;
        int soff = (ky * 34 + kx) * IN_PITCH;
        const uint32_t* wh = sm + WOFF + buf * (2 * WPLANE);
        const uint32_t* wl = wh + WPLANE;
        const uint32_t* ih = sm;
        const uint32_t* il = sm + PLANE;
        #pragma unroll
        for (int q = 0; q < 4; q++) {
            uint32_t ah[2][4], al[2][4];
            #pragma unroll
            for (int mt = 0; mt < 2; mt++) {
                int aw = awbase + mt * (16 * IN_PITCH) + q * 8;
                ah[mt][0] = wh[aw];      ah[mt][1] = wh[aw + 8 * IN_PITCH];
                ah[mt][2] = wh[aw + 4];  ah[mt][3] = wh[aw + 8 * IN_PITCH + 4];
                al[mt][0] = wl[aw];      al[mt][1] = wl[aw + 8 * IN_PITCH];
                al[mt][2] = wl[aw + 4];  al[mt][3] = wl[aw + 8 * IN_PITCH + 4];
            }
            #pragma unroll
            for (int j = 0; j < 4; j++) {
                int bw = bword[j] + soff + q * 8;
                uint32_t bh0 = ih[bw], bh1 = ih[bw + 4];
                uint32_t bl0 = il[bw], bl1 = il[bw + 4];
                #pragma unroll
                for (int mt = 0; mt < 2; mt++) {
                    mma_bf16(acc[mt][j], ah[mt][0], ah[mt][1], ah[mt][2], ah[mt][3], bh0, bh1);
                    mma_bf16(acc[mt][j], ah[mt][0], ah[mt][1], ah[mt][2], ah[mt][3], bl0, bl1);
                    mma_bf16(acc[mt][j], al[mt][0], al[mt][1], al[mt][2], al[mt][3], bh0, bh1);
                }
            }
        }
    }

    // ---- epilogue: transpose through smem (fp32, pitch 68), then coalesced out ----
    float* smf = reinterpret_cast<float*>(sm);
    __syncthreads();
    {
        #pragma unroll
        for (int mt = 0; mt < 2; mt++) {
            int col = cobase + mt * 16 + (lane >> 2);
            #pragma unroll
            for (int j = 0; j < 4; j++) {
                int p0 = pxbase + j * 8 + (lane & 3) * 2;
                smf[p0 * 68 + col]            = acc[mt][j][0];
                smf[(p0 + 1) * 68 + col]      = acc[mt][j][1];
                smf[p0 * 68 + col + 8]        = acc[mt][j][2];
                smf[(p0 + 1) * 68 + col + 8]  = acc[mt][j][3];
            }
        }
    }
    __syncthreads();
    size_t obase = ((size_t)b * HW + g * 128) * 64;
    for (int idx = t; idx < 2048; idx += 256) {          // 128 px * 16 chunks of 4 co
        int px = idx >> 4, ck = idx & 15;
        float4 v = *reinterpret_cast<const float4*>(smf + px * 68 + ck * 4);
        size_t go = obase + (size_t)px * 64 + ck * 4;
        if (reshi) {
            uint2 rh = *reinterpret_cast<const uint2*>(reshi + go);
            uint2 rl = *reinterpret_cast<const uint2*>(reslo + go);
            const __nv_bfloat162* h2 = reinterpret_cast<const __nv_bfloat162*>(&rh);
            const __nv_bfloat162* l2 = reinterpret_cast<const __nv_bfloat162*>(&rl);
            float2 a0 = __bfloat1622float2(h2[0]), a1 = __bfloat1622float2(h2[1]);
            float2 c0 = __bfloat1622float2(l2[0]), c1 = __bfloat1622float2(l2[1]);
            v.x += a0.x + c0.x; v.y += a0.y + c0.y;
            v.z += a1.x + c1.x; v.w += a1.y + c1.y;
        }
        v.x = fmaxf(v.x, 0.f); v.y = fmaxf(v.y, 0.f);
        v.z = fmaxf(v.z, 0.f); v.w = fmaxf(v.w, 0.f);
        __nv_bfloat16 h[4], l[4];
        split_bf16(v.x, h[0], l[0]); split_bf16(v.y, h[1], l[1]);
        split_bf16(v.z, h[2], l[2]); split_bf16(v.w, h[3], l[3]);
        *reinterpret_cast<uint2*>(outhi + go) = *reinterpret_cast<uint2*>(h);
        *reinterpret_cast<uint2*>(outlo + go) = *reinterpret_cast<uint2*>(l);
    }
}

// ---------------- GAP over hi/lo NHWC ----------------
__global__ void gap_nhwc(const __nv_bfloat16* __restrict__ inhi,
                         const __nv_bfloat16* __restrict__ inlo, float* __restrict__ gap) {
    __shared__ float part[4][64];
    int b = blockIdx.x, t = threadIdx.x, ci = t & 63, q = t >> 6;
    const __nv_bfloat16* hb = inhi + (size_t)b * HW * 64;
    const __nv_bfloat16* lb = inlo + (size_t)b * HW * 64;
    float s = 0.0f;
    for (int px = q * 256; px < q * 256 + 256; px++) {
        size_t o = (size_t)px * 64 + ci;
        s += __bfloat162float(hb[o]) + __bfloat162float(lb[o]);
    }
    part[q][ci] = s;
    __syncthreads();
    if (t < 64)
        gap[b * 64 + t] = (part[0][t] + part[1][t] + part[2][t] + part[3][t]) * (1.0f / 1024.0f);
}

// ---------------- resnet FC + masked merge into d_out ----------------
__global__ void fc_merge(const float* __restrict__ gap, const float* __restrict__ rfc,
                         const float* __restrict__ rfb, const int* __restrict__ flag,
                         float* out) {
    __shared__ float sg[64];
    int b = blockIdx.x, t = threadIdx.x;
    sg[t] = gap[b * 64 + t];
    __syncthreads();
    if (t < 10) {
        float a = rfb[t];
        #pragma unroll
        for (int k = 0; k < 64; k++) a = fmaf(sg[k], rfc[k * 10 + t], a);
        if (flag[b]) out[(size_t)b * 10 + t] = a;
    }
}

// ---------------- launcher ----------------
extern "C" void kernel_launch(void* const* d_in, const int* in_sizes, int n_in,
                              void* d_out, int out_size) {
    const float* x    = (const float*)d_in[0];
    const float* thr  = (const float*)d_in[1];
    const int*   lab  = (const int*)d_in[2];
    const float* lw1  = (const float*)d_in[3];
    const float* lb1  = (const float*)d_in[4];
    const float* lw2  = (const float*)d_in[5];
    const float* lb2  = (const float*)d_in[6];
    const float* lfc1 = (const float*)d_in[7];
    const float* lfb1 = (const float*)d_in[8];
    const float* lfc2 = (const float*)d_in[9];
    const float* lfb2 = (const float*)d_in[10];
    const float* lfc3 = (const float*)d_in[11];
    const float* lfb3 = (const float*)d_in[12];
    const float* rw0  = (const float*)d_in[13];
    const float* rb0  = (const float*)d_in[14];
    const float* rw1a = (const float*)d_in[15];
    const float* rb1a = (const float*)d_in[16];
    const float* rw1b = (const float*)d_in[17];
    const float* rb1b = (const float*)d_in[18];
    const float* rw2a = (const float*)d_in[19];
    const float* rb2a = (const float*)d_in[20];
    const float* rw2b = (const float*)d_in[21];
    const float* rb2b = (const float*)d_in[22];
    const float* rfc  = (const float*)d_in[23];
    const float* rfb  = (const float*)d_in[24];

    float* out  = (float*)d_out;
    float* conf = out + BATCH * 10;

    __nv_bfloat16 *Hhi, *Hlo, *Rhi, *Rlo, *Whi, *Wlo;
    float *gapb; int* flag;
    cudaGetSymbolAddress((void**)&Hhi,  g_Hhi);
    cudaGetSymbolAddress((void**)&Hlo,  g_Hlo);
    cudaGetSymbolAddress((void**)&Rhi,  g_Rhi);
    cudaGetSymbolAddress((void**)&Rlo,  g_Rlo);
    cudaGetSymbolAddress((void**)&Whi,  g_Whi);
    cudaGetSymbolAddress((void**)&Wlo,  g_Wlo);
    cudaGetSymbolAddress((void**)&gapb, g_gap);
    cudaGetSymbolAddress((void**)&flag, g_flag);

    cudaFuncSetAttribute(conv_mma, cudaFuncAttributeMaxDynamicSharedMemorySize, SMEM_BYTES);

    const int WL = 9 * 64 * 72;
    prep_w<<<(WL + 255) / 256, 256>>>(rw1a, Whi + 0 * WL, Wlo + 0 * WL);
    prep_w<<<(WL + 255) / 256, 256>>>(rw1b, Whi + 1 * WL, Wlo + 1 * WL);
    prep_w<<<(WL + 255) / 256, 256>>>(rw2a, Whi + 2 * WL, Wlo + 2 * WL);
    prep_w<<<(WL + 255) / 256, 256>>>(rw2b, Whi + 3 * WL, Wlo + 3 * WL);

    zero_conf<<<1, 128>>>(conf);

    // LeNet branch (fully fused)
    lenet_all<<<BATCH, 256>>>(x, lw1, lb1, lw2, lb2, lfc1, lfb1, lfc2, lfb2,
                              lfc3, lfb3, thr, lab, out, conf, flag);

    // ResNet branch (hi/lo bf16 NHWC activations)
    dim3 g0(BATCH, 4);
    conv0_k<<<g0, 256>>>(x, rw0, rb0, Hhi, Hlo);
    dim3 g(BATCH, 8);
    conv_mma<<<g, 256, SMEM_BYTES>>>(Hhi, Hlo, Whi + 0 * WL, Wlo + 0 * WL, rb1a,
                                     nullptr, nullptr, Rhi, Rlo);
    conv_mma<<<g, 256, SMEM_BYTES>>>(Rhi, Rlo, Whi + 1 * WL, Wlo + 1 * WL, rb1b,
                                     Hhi, Hlo, Hhi, Hlo);
    conv_mma<<<g, 256, SMEM_BYTES>>>(Hhi, Hlo, Whi + 2 * WL, Wlo + 2 * WL, rb2a,
                                     nullptr, nullptr, Rhi, Rlo);
    conv_mma<<<g, 256, SMEM_BYTES>>>(Rhi, Rlo, Whi + 3 * WL, Wlo + 3 * WL, rb2b,
                                     Hhi, Hlo, Hhi, Hlo);

    gap_nhwc<<<BATCH, 256>>>(Hhi, Hlo, gapb);
    fc_merge<<<BATCH, 64>>>(gapb, rfc, rfb, flag, out);
}

// round 11
// speedup vs baseline: 1.0007x; 1.0007x over previous
#include <cuda_runtime.h>
#include <cuda_bf16.h>
#include <cstdint>
#include <cstddef>

#define BATCH 1024
#define HW 1024   // 32*32

// ---------------- scratch (device globals; no allocs allowed) ----------------
__device__ __nv_bfloat16 g_Hhi[(size_t)BATCH * HW * 64];  // 128 MB each
__device__ __nv_bfloat16 g_Hlo[(size_t)BATCH * HW * 64];
__device__ __nv_bfloat16 g_Rhi[(size_t)BATCH * HW * 64];
__device__ __nv_bfloat16 g_Rlo[(size_t)BATCH * HW * 64];
__device__ __nv_bfloat16 g_Whi[4 * 9 * 64 * 72];
__device__ __nv_bfloat16 g_Wlo[4 * 9 * 64 * 72];
__device__ float g_gap[BATCH * 64];
__device__ int   g_flag[BATCH];

// ---------------- misc ----------------
__global__ void zero_conf(float* conf) {
    int t = threadIdx.x;
    if (t < 100) conf[t] = 0.0f;
}

// weight prep: OIHW fp32 [64][64][3][3] -> [s=9][co=64][ci pad 72] bf16 hi/lo
__global__ void prep_w(const float* __restrict__ w, __nv_bfloat16* __restrict__ whi,
                       __nv_bfloat16* __restrict__ wlo) {
    int idx = blockIdx.x * 256 + threadIdx.x;          // 9*64*72 = 41472
    if (idx >= 9 * 64 * 72) return;
    int s = idx / (64 * 72), rem = idx % (64 * 72), co = rem / 72, ci = rem % 72;
    float v = 0.0f;
    if (ci < 64) v = w[(co * 64 + ci) * 9 + s];
    __nv_bfloat16 h = __float2bfloat16(v);
    whi[idx] = h;
    wlo[idx] = __float2bfloat16(v - __bfloat162float(h));
}

// ---------------- fused LeNet ----------------
__global__ __launch_bounds__(256) void lenet_all(
        const float* __restrict__ x, const float* __restrict__ w1, const float* __restrict__ b1,
        const float* __restrict__ w2, const float* __restrict__ b2,
        const float* __restrict__ fc1w, const float* __restrict__ fc1b,
        const float* __restrict__ fc2w, const float* __restrict__ fc2b,
        const float* __restrict__ fc3w, const float* __restrict__ fc3b,
        const float* __restrict__ thr_p, const int* __restrict__ labels,
        float* __restrict__ lenout, float* conf, int* __restrict__ flag) {
    __shared__ float sx[3 * 32 * 32];
    __shared__ float sw[2400];
    __shared__ float p1[1176];
    __shared__ float p2[400];
    __shared__ float h1[120];
    __shared__ float h2[84];
    __shared__ float lg[10];
    __shared__ float sb[16];
    int bid = blockIdx.x, t = threadIdx.x;
    const float* xb = x + (size_t)bid * 3072;
    for (int i = t; i < 3072; i += 256) sx[i] = xb[i];
    for (int i = t; i < 450; i += 256) sw[i] = w1[i];
    if (t < 6) sb[t] = b1[t];
    __syncthreads();
    for (int idx = t; idx < 6 * 14 * 14; idx += 256) {
        int c = idx / 196, py = (idx / 14) % 14, px = idx % 14;
        float m = -1e30f;
        #pragma unroll
        for (int dy = 0; dy < 2; dy++)
            #pragma unroll
            for (int dx = 0; dx < 2; dx++) {
                int y = 2 * py + dy, x0 = 2 * px + dx;
                float a = sb[c];
                for (int ci = 0; ci < 3; ci++)
                    #pragma unroll
                    for (int ky = 0; ky < 5; ky++)
                        #pragma unroll
                        for (int kx = 0; kx < 5; kx++)
                            a = fmaf(sx[ci * 1024 + (y + ky) * 32 + (x0 + kx)],
                                     sw[(c * 3 + ci) * 25 + ky * 5 + kx], a);
                m = fmaxf(m, a);
            }
        p1[idx] = fmaxf(m, 0.0f);
    }
    __syncthreads();
    for (int i = t; i < 2400; i += 256) sw[i] = w2[i];
    if (t < 16) sb[t] = b2[t];
    __syncthreads();
    for (int idx = t; idx < 400; idx += 256) {
        int c = idx / 25, py = (idx / 5) % 5, px = idx % 5;
        float m = -1e30f;
        #pragma unroll
        for (int dy = 0; dy < 2; dy++)
            #pragma unroll
            for (int dx = 0; dx < 2; dx++) {
                int y = 2 * py + dy, x0 = 2 * px + dx;
                float a = sb[c];
                for (int ci = 0; ci < 6; ci++)
                    #pragma unroll
                    for (int ky = 0; ky < 5; ky++)
                        #pragma unroll
                        for (int kx = 0; kx < 5; kx++)
                            a = fmaf(p1[ci * 196 + (y + ky) * 14 + (x0 + kx)],
                                     sw[(c * 6 + ci) * 25 + ky * 5 + kx], a);
                m = fmaxf(m, a);
            }
        p2[idx] = fmaxf(m, 0.0f);
    }
    __syncthreads();
    if (t < 120) {
        float a = fc1b[t];
        for (int k = 0; k < 400; k++) a = fmaf(p2[k], fc1w[k * 120 + t], a);
        h1[t] = fmaxf(a, 0.0f);
    }
    __syncthreads();
    if (t < 84) {
        float a = fc2b[t];
        for (int k = 0; k < 120; k++) a = fmaf(h1[k], fc2w[k * 84 + t], a);
        h2[t] = fmaxf(a, 0.0f);
    }
    __syncthreads();
    if (t < 10) {
        float a = fc3b[t];
        for (int k = 0; k < 84; k++) a = fmaf(h2[k], fc3w[k * 10 + t], a);
        lg[t] = a;
        lenout[(size_t)bid * 10 + t] = a;
    }
    __syncthreads();
    if (t == 0) {
        float m = lg[0]; int am = 0;
        #pragma unroll
        for (int i = 1; i < 10; i++) if (lg[i] > m) { m = lg[i]; am = i; }
        float p[10]; float s = 0.0f;
        #pragma unroll
        for (int i = 0; i < 10; i++) { p[i] = expf(lg[i] - m); s += p[i]; }
        float inv = 1.0f / s;
        float p0 = -1.0f, pp1 = -1.0f;
        #pragma unroll
        for (int i = 0; i < 10; i++) {
            float v = p[i] * inv;
            if (v > p0) { pp1 = p0; p0 = v; } else if (v > pp1) { pp1 = v; }
        }
        flag[bid] = ((p0 - pp1) <= thr_p[0]) ? 1 : 0;
        atomicAdd(&conf[labels[bid] * 10 + am], 1.0f);
    }
}

// ---------------- split helper ----------------
__device__ __forceinline__ void split_bf16(float v, __nv_bfloat16& h, __nv_bfloat16& l) {
    h = __float2bfloat16(v);
    l = __float2bfloat16(v - __bfloat162float(h));
}

// ---------------- ResNet conv0 (3->64, fp32 direct), hi/lo NHWC out + ReLU ----------------
__global__ __launch_bounds__(256, 2) void conv0_k(const float* __restrict__ x,
        const float* __restrict__ w, const float* __restrict__ bias,
        __nv_bfloat16* __restrict__ ohi, __nv_bfloat16* __restrict__ olo) {
    __shared__ __align__(16) float s_in[3 * 10 * 36];
    __shared__ float s_w[3 * 64 * 9];
    int b = blockIdx.x, row0 = blockIdx.y * 8;
    int t = threadIdx.x, warp = t >> 5, lane = t & 31;
    int r2 = lane >> 3, colg = lane & 7, cob = warp * 8;

    float acc[2][4][8];
    #pragma unroll
    for (int oc = 0; oc < 8; oc++) {
        float bv = bias[cob + oc];
        #pragma unroll
        for (int rr = 0; rr < 2; rr++)
            #pragma unroll
            for (int cc = 0; cc < 4; cc++) acc[rr][cc][oc] = bv;
    }
    const float* inb = x + (size_t)b * 3 * HW;
    for (int idx = t; idx < 3 * 340; idx += 256) {
        int kc = idx / 340, rem = idx % 340, r = rem / 34, c = rem % 34;
        int gr = row0 - 1 + r, gc = c - 1;
        float v = 0.0f;
        if ((unsigned)gr < 32u && (unsigned)gc < 32u)
            v = inb[(size_t)kc * HW + gr * 32 + gc];
        s_in[kc * 360 + r * 36 + c] = v;
    }
    for (int idx = t; idx < 3 * 576; idx += 256) {
        int kc = idx / 576, rem = idx % 576, co = rem / 9, k = rem % 9;
        s_w[idx] = w[((size_t)co * 3 + kc) * 9 + k];
    }
    __syncthreads();
    #pragma unroll
    for (int kc = 0; kc < 3; kc++) {
        float xin[4][6];
        const float* sbase = s_in + kc * 360 + (r2 * 2) * 36 + colg * 4;
        #pragma unroll
        for (int r = 0; r < 4; r++) {
            float4 a = *reinterpret_cast<const float4*>(sbase + r * 36);
            float2 bv = *reinterpret_cast<const float2*>(sbase + r * 36 + 4);
            xin[r][0] = a.x; xin[r][1] = a.y; xin[r][2] = a.z; xin[r][3] = a.w;
            xin[r][4] = bv.x; xin[r][5] = bv.y;
        }
        const float* wp = s_w + kc * 576 + cob * 9;
        #pragma unroll
        for (int oc = 0; oc < 8; oc++) {
            float w0 = wp[oc * 9], w1 = wp[oc * 9 + 1], w2 = wp[oc * 9 + 2];
            float w3 = wp[oc * 9 + 3], w4 = wp[oc * 9 + 4], w5 = wp[oc * 9 + 5];
            float w6 = wp[oc * 9 + 6], w7 = wp[oc * 9 + 7], w8 = wp[oc * 9 + 8];
            #pragma unroll
            for (int rr = 0; rr < 2; rr++)
                #pragma unroll
                for (int cc = 0; cc < 4; cc++) {
                    float a = acc[rr][cc][oc];
                    a = fmaf(xin[rr][cc],     w0, a);
                    a = fmaf(xin[rr][cc + 1], w1, a);
                    a = fmaf(xin[rr][cc + 2], w2, a);
                    a = fmaf(xin[rr + 1][cc],     w3, a);
                    a = fmaf(xin[rr + 1][cc + 1], w4, a);
                    a = fmaf(xin[rr + 1][cc + 2], w5, a);
                    a = fmaf(xin[rr + 2][cc],     w6, a);
                    a = fmaf(xin[rr + 2][cc + 1], w7, a);
                    a = fmaf(xin[rr + 2][cc + 2], w8, a);
                    acc[rr][cc][oc] = a;
                }
        }
    }
    size_t ob = (size_t)b * HW * 64;
    #pragma unroll
    for (int rr = 0; rr < 2; rr++)
        #pragma unroll
        for (int cc = 0; cc < 4; cc++) {
            int px = (row0 + r2 * 2 + rr) * 32 + colg * 4 + cc;
            __nv_bfloat16 hv[8], lv[8];
            #pragma unroll
            for (int oc = 0; oc < 8; oc++)
                split_bf16(fmaxf(acc[rr][cc][oc], 0.f), hv[oc], lv[oc]);
            *reinterpret_cast<uint4*>(ohi + ob + (size_t)px * 64 + cob) =
                *reinterpret_cast<uint4*>(hv);
            *reinterpret_cast<uint4*>(olo + ob + (size_t)px * 64 + cob) =
                *reinterpret_cast<uint4*>(lv);
        }
}

// ---------------- bf16x3 tensor-core 3x3 SAME conv, 64->64, hi/lo NHWC ----------------
__device__ __forceinline__ void mma_bf16(float* d, uint32_t a0, uint32_t a1, uint32_t a2,
                                         uint32_t a3, uint32_t b0, uint32_t b1) {
    asm volatile("mma.sync.aligned.m16n8k16.row.col.f32.bf16.bf16.f32 "
                 "{%0,%1,%2,%3}, {%4,%5,%6,%7}, {%8,%9}, {%0,%1,%2,%3};"
                 : "+f"(d[0]), "+f"(d[1]), "+f"(d[2]), "+f"(d[3])
                 : "r"(a0), "r"(a1), "r"(a2), "r"(a3), "r"(b0), "r"(b1));
}
__device__ __forceinline__ void ldsm4(uint32_t& r0, uint32_t& r1, uint32_t& r2, uint32_t& r3,
                                      uint32_t addr) {
    asm volatile("ldmatrix.sync.aligned.m8n8.x4.shared.b16 {%0,%1,%2,%3}, [%4];"
                 : "=r"(r0), "=r"(r1), "=r"(r2), "=r"(r3) : "r"(addr));
}

#define IN_PITCH 36                 // words per px row (64 ci bf16 data + pad)
#define PLANE    7344               // 204 px (6 rows x 34 cols) * 36 words
#define WOFF     14688              // W buffers start (words)
#define WPLANE   2304               // 64 co * 36 words
#define SMEM_WORDS (WOFF + 2 * 2 * WPLANE)          // 23904
#define SMEM_BYTES (SMEM_WORDS * 4)                 // 95616

// Warp tiling: 8 warps = 4 px-groups (32 px) x 2 co-groups (32 co).
__global__ __launch_bounds__(256, 2) void conv_mma(
        const __nv_bfloat16* __restrict__ inhi,   // [B][1024][64]
        const __nv_bfloat16* __restrict__ inlo,
        const __nv_bfloat16* __restrict__ whi,    // [9][64][72]
        const __nv_bfloat16* __restrict__ wlo,
        const float* __restrict__ bias,
        const __nv_bfloat16* reshi, const __nv_bfloat16* reslo,
        __nv_bfloat16* __restrict__ outhi, __nv_bfloat16* __restrict__ outlo) {
    extern __shared__ uint32_t sm[];
    uint32_t sbase = (uint32_t)__cvta_generic_to_shared(sm);
    int b = blockIdx.x, g = blockIdx.y, r0 = g * 4;
    int t = threadIdx.x, lane = t & 31, warp = t >> 5;
    int cobase = (warp >> 2) * 32;           // 2 co-groups of 32
    int pxbase = (warp & 3) * 32;            // 4 px-groups of 32

    // ---- stage input tile via cp.async: 6 rows x 34 cols, hi+lo planes ----
    const __nv_bfloat16* hbase = inhi + (size_t)b * HW * 64;
    const __nv_bfloat16* lbase = inlo + (size_t)b * HW * 64;
    for (int idx = t; idx < 3264; idx += 256) {          // 2 planes * 204 px * 8 chunks
        int plane = idx >= 1632;
        int rem = idx - plane * 1632;
        int pxt = rem >> 3, ck = rem & 7;
        int rt = pxt / 34, ct = pxt % 34;
        int gr = r0 - 1 + rt, gc = ct - 1;
        int ok = ((unsigned)gr < 32u) && ((unsigned)gc < 32u);
        const __nv_bfloat16* base = plane ? lbase : hbase;
        const char* src = reinterpret_cast<const char*>(
            base + (ok ? ((size_t)(gr * 32 + gc)) * 64 + ck * 8 : 0));
        uint32_t dst = (uint32_t)__cvta_generic_to_shared(
            sm + plane * PLANE + pxt * IN_PITCH + ck * 4);
        int sz = ok ? 16 : 0;
        asm volatile("cp.async.ca.shared.global [%0], [%1], 16, %2;"
                     :: "r"(dst), "l"(src), "r"(sz));
    }

    // ---- cp.async weight staging, per shift, double buffered ----
    auto issueW = [&](int s, int buf) {
        for (int c = t; c < 1152; c += 256) {            // 2 planes * 576 16B chunks
            int plane = (c >= 576) ? 1 : 0;
            int cc = c - plane * 576;
            const char* src = reinterpret_cast<const char*>(plane ? wlo : whi)
                              + (size_t)s * 9216 + cc * 16;
            uint32_t dst = (uint32_t)__cvta_generic_to_shared(
                sm + WOFF + buf * (2 * WPLANE) + plane * WPLANE + cc * 4);
            asm volatile("cp.async.ca.shared.global [%0], [%1], 16;" :: "r"(dst), "l"(src));
        }
        asm volatile("cp.async.commit_group;" ::: "memory");
    };
    issueW(0, 0);

    // ---- accumulators ----
    float acc[2][4][4];
    #pragma unroll
    for (int mt = 0; mt < 2; mt++) {
        float bv0 = bias[cobase + mt * 16 + (lane >> 2)];
        float bv1 = bias[cobase + mt * 16 + (lane >> 2) + 8];
        #pragma unroll
        for (int j = 0; j < 4; j++) {
            acc[mt][j][0] = bv0; acc[mt][j][1] = bv0;
            acc[mt][j][2] = bv1; acc[mt][j][3] = bv1;
        }
    }

    // ---- ldmatrix per-lane word offsets ----
    // A (weights): tile = lane>>3: mhalf = tile&1, khalf = tile>>1; row = lane&7
    int a_mhalf = (lane >> 3) & 1, a_khalf = lane >> 4, a_row = lane & 7;
    int aoff[2];
    #pragma unroll
    for (int mt = 0; mt < 2; mt++)
        aoff[mt] = (cobase + mt * 16 + a_mhalf * 8 + a_row) * IN_PITCH + a_khalf * 4;
    // B (activations): grp = lane>>3: pxg = grp>>1, khalf = grp&1; row = lane&7
    int b_pxg = lane >> 4, b_khalf = (lane >> 3) & 1, b_row = lane & 7;
    int boff[2];
    #pragma unroll
    for (int jp = 0; jp < 2; jp++) {
        int p = pxbase + jp * 16 + b_pxg * 8 + b_row;
        int rr = p >> 5, cc = p & 31;
        boff[jp] = (rr * 34 + cc) * IN_PITCH + b_khalf * 4;
    }

    // ---- main loop over 9 shifts ----
    for (int s = 0; s < 9; s++) {
        int buf = s & 1;
        asm volatile("cp.async.wait_group 0;" ::: "memory");
        __syncthreads();
        if (s < 8) issueW(s + 1, buf ^ 1);
        int ky = s / 3, kx = s - 3 * ky;
        int soff = (ky * 34 + kx) * IN_PITCH;
        uint32_t whB = sbase + (WOFF + buf * (2 * WPLANE)) * 4;
        uint32_t wlB = whB + WPLANE * 4;
        uint32_t ihB = sbase + soff * 4;
        uint32_t ilB = ihB + PLANE * 4;
        #pragma unroll
        for (int q = 0; q < 4; q++) {
            // fragments: A hi/lo for both mt; B hi/lo for both j-pairs
            uint32_t ah[2][4], al[2][4], bh[2][4], bl[2][4];
            #pragma unroll
            for (int mt = 0; mt < 2; mt++) {
                ldsm4(ah[mt][0], ah[mt][1], ah[mt][2], ah[mt][3],
                      whB + (aoff[mt] + q * 8) * 4);
                ldsm4(al[mt][0], al[mt][1], al[mt][2], al[mt][3],
                      wlB + (aoff[mt] + q * 8) * 4);
            }
            #pragma unroll
            for (int jp = 0; jp < 2; jp++) {
                ldsm4(bh[jp][0], bh[jp][1], bh[jp][2], bh[jp][3],
                      ihB + (boff[jp] + q * 8) * 4);
                ldsm4(bl[jp][0], bl[jp][1], bl[jp][2], bl[jp][3],
                      ilB + (boff[jp] + q * 8) * 4);
            }
            // term-major MMA order: breaks same-accumulator chains (reuse distance 8)
            #pragma unroll
            for (int mt = 0; mt < 2; mt++)
                #pragma unroll
                for (int j = 0; j < 4; j++) {
                    int jp = j >> 1, hf = (j & 1) * 2;
                    mma_bf16(acc[mt][j], ah[mt][0], ah[mt][1], ah[mt][2], ah[mt][3],
                             bh[jp][hf], bh[jp][hf + 1]);
                }
            #pragma unroll
            for (int mt = 0; mt < 2; mt++)
                #pragma unroll
                for (int j = 0; j < 4; j++) {
                    int jp = j >> 1, hf = (j & 1) * 2;
                    mma_bf16(acc[mt][j], ah[mt][0], ah[mt][1], ah[mt][2], ah[mt][3],
                             bl[jp][hf], bl[jp][hf + 1]);
                }
            #pragma unroll
            for (int mt = 0; mt < 2; mt++)
                #pragma unroll
                for (int j = 0; j < 4; j++) {
                    int jp = j >> 1, hf = (j & 1) * 2;
                    mma_bf16(acc[mt][j], al[mt][0], al[mt][1], al[mt][2], al[mt][3],
                             bh[jp][hf], bh[jp][hf + 1]);
                }
        }
    }

    // ---- epilogue: transpose through smem (fp32, pitch 68), then coalesced out ----
    float* smf = reinterpret_cast<float*>(sm);
    __syncthreads();
    {
        #pragma unroll
        for (int mt = 0; mt < 2; mt++) {
            int col = cobase + mt * 16 + (lane >> 2);
            #pragma unroll
            for (int j = 0; j < 4; j++) {
                int p0 = pxbase + j * 8 + (lane & 3) * 2;
                smf[p0 * 68 + col]            = acc[mt][j][0];
                smf[(p0 + 1) * 68 + col]      = acc[mt][j][1];
                smf[p0 * 68 + col + 8]        = acc[mt][j][2];
                smf[(p0 + 1) * 68 + col + 8]  = acc[mt][j][3];
            }
        }
    }
    __syncthreads();
    size_t obase = ((size_t)b * HW + g * 128) * 64;
    for (int idx = t; idx < 2048; idx += 256) {          // 128 px * 16 chunks of 4 co
        int px = idx >> 4, ck = idx & 15;
        float4 v = *reinterpret_cast<const float4*>(smf + px * 68 + ck * 4);
        size_t go = obase + (size_t)px * 64 + ck * 4;
        if (reshi) {
            uint2 rh = *reinterpret_cast<const uint2*>(reshi + go);
            uint2 rl = *reinterpret_cast<const uint2*>(reslo + go);
            const __nv_bfloat162* h2 = reinterpret_cast<const __nv_bfloat162*>(&rh);
            const __nv_bfloat162* l2 = reinterpret_cast<const __nv_bfloat162*>(&rl);
            float2 a0 = __bfloat1622float2(h2[0]), a1 = __bfloat1622float2(h2[1]);
            float2 c0 = __bfloat1622float2(l2[0]), c1 = __bfloat1622float2(l2[1]);
            v.x += a0.x + c0.x; v.y += a0.y + c0.y;
            v.z += a1.x + c1.x; v.w += a1.y + c1.y;
        }
        v.x = fmaxf(v.x, 0.f); v.y = fmaxf(v.y, 0.f);
        v.z = fmaxf(v.z, 0.f); v.w = fmaxf(v.w, 0.f);
        __nv_bfloat16 h[4], l[4];
        split_bf16(v.x, h[0], l[0]); split_bf16(v.y, h[1], l[1]);
        split_bf16(v.z, h[2], l[2]); split_bf16(v.w, h[3], l[3]);
        *reinterpret_cast<uint2*>(outhi + go) = *reinterpret_cast<uint2*>(h);
        *reinterpret_cast<uint2*>(outlo + go) = *reinterpret_cast<uint2*>(l);
    }
}

// ---------------- GAP over hi/lo NHWC ----------------
__global__ void gap_nhwc(const __nv_bfloat16* __restrict__ inhi,
                         const __nv_bfloat16* __restrict__ inlo, float* __restrict__ gap) {
    __shared__ float part[4][64];
    int b = blockIdx.x, t = threadIdx.x, ci = t & 63, q = t >> 6;
    const __nv_bfloat16* hb = inhi + (size_t)b * HW * 64;
    const __nv_bfloat16* lb = inlo + (size_t)b * HW * 64;
    float s = 0.0f;
    for (int px = q * 256; px < q * 256 + 256; px++) {
        size_t o = (size_t)px * 64 + ci;
        s += __bfloat162float(hb[o]) + __bfloat162float(lb[o]);
    }
    part[q][ci] = s;
    __syncthreads();
    if (t < 64)
        gap[b * 64 + t] = (part[0][t] + part[1][t] + part[2][t] + part[3][t]) * (1.0f / 1024.0f);
}

// ---------------- resnet FC + masked merge into d_out ----------------
__global__ void fc_merge(const float* __restrict__ gap, const float* __restrict__ rfc,
                         const float* __restrict__ rfb, const int* __restrict__ flag,
                         float* out) {
    __shared__ float sg[64];
    int b = blockIdx.x, t = threadIdx.x;
    sg[t] = gap[b * 64 + t];
    __syncthreads();
    if (t < 10) {
        float a = rfb[t];
        #pragma unroll
        for (int k = 0; k < 64; k++) a = fmaf(sg[k], rfc[k * 10 + t], a);
        if (flag[b]) out[(size_t)b * 10 + t] = a;
    }
}

// ---------------- launcher ----------------
extern "C" void kernel_launch(void* const* d_in, const int* in_sizes, int n_in,
                              void* d_out, int out_size) {
    const float* x    = (const float*)d_in[0];
    const float* thr  = (const float*)d_in[1];
    const int*   lab  = (const int*)d_in[2];
    const float* lw1  = (const float*)d_in[3];
    const float* lb1  = (const float*)d_in[4];
    const float* lw2  = (const float*)d_in[5];
    const float* lb2  = (const float*)d_in[6];
    const float* lfc1 = (const float*)d_in[7];
    const float* lfb1 = (const float*)d_in[8];
    const float* lfc2 = (const float*)d_in[9];
    const float* lfb2 = (const float*)d_in[10];
    const float* lfc3 = (const float*)d_in[11];
    const float* lfb3 = (const float*)d_in[12];
    const float* rw0  = (const float*)d_in[13];
    const float* rb0  = (const float*)d_in[14];
    const float* rw1a = (const float*)d_in[15];
    const float* rb1a = (const float*)d_in[16];
    const float* rw1b = (const float*)d_in[17];
    const float* rb1b = (const float*)d_in[18];
    const float* rw2a = (const float*)d_in[19];
    const float* rb2a = (const float*)d_in[20];
    const float* rw2b = (const float*)d_in[21];
    const float* rb2b = (const float*)d_in[22];
    const float* rfc  = (const float*)d_in[23];
    const float* rfb  = (const float*)d_in[24];

    float* out  = (float*)d_out;
    float* conf = out + BATCH * 10;

    __nv_bfloat16 *Hhi, *Hlo, *Rhi, *Rlo, *Whi, *Wlo;
    float *gapb; int* flag;
    cudaGetSymbolAddress((void**)&Hhi,  g_Hhi);
    cudaGetSymbolAddress((void**)&Hlo,  g_Hlo);
    cudaGetSymbolAddress((void**)&Rhi,  g_Rhi);
    cudaGetSymbolAddress((void**)&Rlo,  g_Rlo);
    cudaGetSymbolAddress((void**)&Whi,  g_Whi);
    cudaGetSymbolAddress((void**)&Wlo,  g_Wlo);
    cudaGetSymbolAddress((void**)&gapb, g_gap);
    cudaGetSymbolAddress((void**)&flag, g_flag);

    cudaFuncSetAttribute(conv_mma, cudaFuncAttributeMaxDynamicSharedMemorySize, SMEM_BYTES);

    const int WL = 9 * 64 * 72;
    prep_w<<<(WL + 255) / 256, 256>>>(rw1a, Whi + 0 * WL, Wlo + 0 * WL);
    prep_w<<<(WL + 255) / 256, 256>>>(rw1b, Whi + 1 * WL, Wlo + 1 * WL);
    prep_w<<<(WL + 255) / 256, 256>>>(rw2a, Whi + 2 * WL, Wlo + 2 * WL);
    prep_w<<<(WL + 255) / 256, 256>>>(rw2b, Whi + 3 * WL, Wlo + 3 * WL);

    zero_conf<<<1, 128>>>(conf);

    // LeNet branch (fully fused)
    lenet_all<<<BATCH, 256>>>(x, lw1, lb1, lw2, lb2, lfc1, lfb1, lfc2, lfb2,
                              lfc3, lfb3, thr, lab, out, conf, flag);

    // ResNet branch (hi/lo bf16 NHWC activations)
    dim3 g0(BATCH, 4);
    conv0_k<<<g0, 256>>>(x, rw0, rb0, Hhi, Hlo);
    dim3 g(BATCH, 8);
    conv_mma<<<g, 256, SMEM_BYTES>>>(Hhi, Hlo, Whi + 0 * WL, Wlo + 0 * WL, rb1a,
                                     nullptr, nullptr, Rhi, Rlo);
    conv_mma<<<g, 256, SMEM_BYTES>>>(Rhi, Rlo, Whi + 1 * WL, Wlo + 1 * WL, rb1b,
                                     Hhi, Hlo, Hhi, Hlo);
    conv_mma<<<g, 256, SMEM_BYTES>>>(Hhi, Hlo, Whi + 2 * WL, Wlo + 2 * WL, rb2a,
                                     nullptr, nullptr, Rhi, Rlo);
    conv_mma<<<g, 256, SMEM_BYTES>>>(Rhi, Rlo, Whi + 3 * WL, Wlo + 3 * WL, rb2b,
                                     Hhi, Hlo, Hhi, Hlo);

    gap_nhwc<<<BATCH, 256>>>(Hhi, Hlo, gapb);
    fc_merge<<<BATCH, 64>>>(gapb, rfc, rfb, flag, out);
}

// round 12
// speedup vs baseline: 1.5007x; 1.4997x over previous
#include <cuda_runtime.h>
#include <cuda_fp16.h>
#include <cstdint>
#include <cstddef>

#define BATCH 1024
#define HW 1024   // 32*32

// ---------------- scratch (device globals; no allocs allowed) ----------------
__device__ __half g_H[(size_t)BATCH * HW * 64];   // 128 MB, fp16 NHWC activations
__device__ __half g_R[(size_t)BATCH * HW * 64];
__device__ __half g_Wh[4 * 9 * 64 * 72];          // fp16 weight hi
__device__ __half g_Wl[4 * 9 * 64 * 72];          // fp16 weight lo (residual)
__device__ float g_gap[BATCH * 64];
__device__ int   g_flag[BATCH];

// ---------------- misc ----------------
__global__ void zero_conf(float* conf) {
    int t = threadIdx.x;
    if (t < 100) conf[t] = 0.0f;
}

// weight prep: OIHW fp32 [64][64][3][3] -> [s=9][co=64][ci pad 72] fp16 hi/lo
__global__ void prep_w(const float* __restrict__ w, __half* __restrict__ wh,
                       __half* __restrict__ wl) {
    int idx = blockIdx.x * 256 + threadIdx.x;          // 9*64*72 = 41472
    if (idx >= 9 * 64 * 72) return;
    int s = idx / (64 * 72), rem = idx % (64 * 72), co = rem / 72, ci = rem % 72;
    float v = 0.0f;
    if (ci < 64) v = w[(co * 64 + ci) * 9 + s];
    __half h = __float2half(v);
    wh[idx] = h;
    wl[idx] = __float2half(v - __half2float(h));
}

// ---------------- fused LeNet (fp32 exact) ----------------
__global__ __launch_bounds__(256) void lenet_all(
        const float* __restrict__ x, const float* __restrict__ w1, const float* __restrict__ b1,
        const float* __restrict__ w2, const float* __restrict__ b2,
        const float* __restrict__ fc1w, const float* __restrict__ fc1b,
        const float* __restrict__ fc2w, const float* __restrict__ fc2b,
        const float* __restrict__ fc3w, const float* __restrict__ fc3b,
        const float* __restrict__ thr_p, const int* __restrict__ labels,
        float* __restrict__ lenout, float* conf, int* __restrict__ flag) {
    __shared__ float sx[3 * 32 * 32];
    __shared__ float sw[2400];
    __shared__ float p1[1176];
    __shared__ float p2[400];
    __shared__ float h1[120];
    __shared__ float h2[84];
    __shared__ float lg[10];
    __shared__ float sb[16];
    int bid = blockIdx.x, t = threadIdx.x;
    const float* xb = x + (size_t)bid * 3072;
    for (int i = t; i < 3072; i += 256) sx[i] = xb[i];
    for (int i = t; i < 450; i += 256) sw[i] = w1[i];
    if (t < 6) sb[t] = b1[t];
    __syncthreads();
    for (int idx = t; idx < 6 * 14 * 14; idx += 256) {
        int c = idx / 196, py = (idx / 14) % 14, px = idx % 14;
        float m = -1e30f;
        #pragma unroll
        for (int dy = 0; dy < 2; dy++)
            #pragma unroll
            for (int dx = 0; dx < 2; dx++) {
                int y = 2 * py + dy, x0 = 2 * px + dx;
                float a = sb[c];
                for (int ci = 0; ci < 3; ci++)
                    #pragma unroll
                    for (int ky = 0; ky < 5; ky++)
                        #pragma unroll
                        for (int kx = 0; kx < 5; kx++)
                            a = fmaf(sx[ci * 1024 + (y + ky) * 32 + (x0 + kx)],
                                     sw[(c * 3 + ci) * 25 + ky * 5 + kx], a);
                m = fmaxf(m, a);
            }
        p1[idx] = fmaxf(m, 0.0f);
    }
    __syncthreads();
    for (int i = t; i < 2400; i += 256) sw[i] = w2[i];
    if (t < 16) sb[t] = b2[t];
    __syncthreads();
    for (int idx = t; idx < 400; idx += 256) {
        int c = idx / 25, py = (idx / 5) % 5, px = idx % 5;
        float m = -1e30f;
        #pragma unroll
        for (int dy = 0; dy < 2; dy++)
            #pragma unroll
            for (int dx = 0; dx < 2; dx++) {
                int y = 2 * py + dy, x0 = 2 * px + dx;
                float a = sb[c];
                for (int ci = 0; ci < 6; ci++)
                    #pragma unroll
                    for (int ky = 0; ky < 5; ky++)
                        #pragma unroll
                        for (int kx = 0; kx < 5; kx++)
                            a = fmaf(p1[ci * 196 + (y + ky) * 14 + (x0 + kx)],
                                     sw[(c * 6 + ci) * 25 + ky * 5 + kx], a);
                m = fmaxf(m, a);
            }
        p2[idx] = fmaxf(m, 0.0f);
    }
    __syncthreads();
    if (t < 120) {
        float a = fc1b[t];
        for (int k = 0; k < 400; k++) a = fmaf(p2[k], fc1w[k * 120 + t], a);
        h1[t] = fmaxf(a, 0.0f);
    }
    __syncthreads();
    if (t < 84) {
        float a = fc2b[t];
        for (int k = 0; k < 120; k++) a = fmaf(h1[k], fc2w[k * 84 + t], a);
        h2[t] = fmaxf(a, 0.0f);
    }
    __syncthreads();
    if (t < 10) {
        float a = fc3b[t];
        for (int k = 0; k < 84; k++) a = fmaf(h2[k], fc3w[k * 10 + t], a);
        lg[t] = a;
        lenout[(size_t)bid * 10 + t] = a;
    }
    __syncthreads();
    if (t == 0) {
        float m = lg[0]; int am = 0;
        #pragma unroll
        for (int i = 1; i < 10; i++) if (lg[i] > m) { m = lg[i]; am = i; }
        float p[10]; float s = 0.0f;
        #pragma unroll
        for (int i = 0; i < 10; i++) { p[i] = expf(lg[i] - m); s += p[i]; }
        float inv = 1.0f / s;
        float p0 = -1.0f, pp1 = -1.0f;
        #pragma unroll
        for (int i = 0; i < 10; i++) {
            float v = p[i] * inv;
            if (v > p0) { pp1 = p0; p0 = v; } else if (v > pp1) { pp1 = v; }
        }
        flag[bid] = ((p0 - pp1) <= thr_p[0]) ? 1 : 0;
        atomicAdd(&conf[labels[bid] * 10 + am], 1.0f);
    }
}

// ---------------- ResNet conv0 (3->64, fp32 direct), fp16 NHWC out + ReLU ----------------
__global__ __launch_bounds__(256, 2) void conv0_k(const float* __restrict__ x,
        const float* __restrict__ w, const float* __restrict__ bias,
        __half* __restrict__ out) {
    __shared__ __align__(16) float s_in[3 * 10 * 36];
    __shared__ float s_w[3 * 64 * 9];
    int b = blockIdx.x, row0 = blockIdx.y * 8;
    int t = threadIdx.x, warp = t >> 5, lane = t & 31;
    int r2 = lane >> 3, colg = lane & 7, cob = warp * 8;

    float acc[2][4][8];
    #pragma unroll
    for (int oc = 0; oc < 8; oc++) {
        float bv = bias[cob + oc];
        #pragma unroll
        for (int rr = 0; rr < 2; rr++)
            #pragma unroll
            for (int cc = 0; cc < 4; cc++) acc[rr][cc][oc] = bv;
    }
    const float* inb = x + (size_t)b * 3 * HW;
    for (int idx = t; idx < 3 * 340; idx += 256) {
        int kc = idx / 340, rem = idx % 340, r = rem / 34, c = rem % 34;
        int gr = row0 - 1 + r, gc = c - 1;
        float v = 0.0f;
        if ((unsigned)gr < 32u && (unsigned)gc < 32u)
            v = inb[(size_t)kc * HW + gr * 32 + gc];
        s_in[kc * 360 + r * 36 + c] = v;
    }
    for (int idx = t; idx < 3 * 576; idx += 256) {
        int kc = idx / 576, rem = idx % 576, co = rem / 9, k = rem % 9;
        s_w[idx] = w[((size_t)co * 3 + kc) * 9 + k];
    }
    __syncthreads();
    #pragma unroll
    for (int kc = 0; kc < 3; kc++) {
        float xin[4][6];
        const float* sbase = s_in + kc * 360 + (r2 * 2) * 36 + colg * 4;
        #pragma unroll
        for (int r = 0; r < 4; r++) {
            float4 a = *reinterpret_cast<const float4*>(sbase + r * 36);
            float2 bv = *reinterpret_cast<const float2*>(sbase + r * 36 + 4);
            xin[r][0] = a.x; xin[r][1] = a.y; xin[r][2] = a.z; xin[r][3] = a.w;
            xin[r][4] = bv.x; xin[r][5] = bv.y;
        }
        const float* wp = s_w + kc * 576 + cob * 9;
        #pragma unroll
        for (int oc = 0; oc < 8; oc++) {
            float w0 = wp[oc * 9], w1 = wp[oc * 9 + 1], w2 = wp[oc * 9 + 2];
            float w3 = wp[oc * 9 + 3], w4 = wp[oc * 9 + 4], w5 = wp[oc * 9 + 5];
            float w6 = wp[oc * 9 + 6], w7 = wp[oc * 9 + 7], w8 = wp[oc * 9 + 8];
            #pragma unroll
            for (int rr = 0; rr < 2; rr++)
                #pragma unroll
                for (int cc = 0; cc < 4; cc++) {
                    float a = acc[rr][cc][oc];
                    a = fmaf(xin[rr][cc],     w0, a);
                    a = fmaf(xin[rr][cc + 1], w1, a);
                    a = fmaf(xin[rr][cc + 2], w2, a);
                    a = fmaf(xin[rr + 1][cc],     w3, a);
                    a = fmaf(xin[rr + 1][cc + 1], w4, a);
                    a = fmaf(xin[rr + 1][cc + 2], w5, a);
                    a = fmaf(xin[rr + 2][cc],     w6, a);
                    a = fmaf(xin[rr + 2][cc + 1], w7, a);
                    a = fmaf(xin[rr + 2][cc + 2], w8, a);
                    acc[rr][cc][oc] = a;
                }
        }
    }
    size_t ob = (size_t)b * HW * 64;
    #pragma unroll
    for (int rr = 0; rr < 2; rr++)
        #pragma unroll
        for (int cc = 0; cc < 4; cc++) {
            int px = (row0 + r2 * 2 + rr) * 32 + colg * 4 + cc;
            __half hv[8];
            #pragma unroll
            for (int oc = 0; oc < 8; oc++)
                hv[oc] = __float2half(fmaxf(acc[rr][cc][oc], 0.f));
            *reinterpret_cast<uint4*>(out + ob + (size_t)px * 64 + cob) =
                *reinterpret_cast<uint4*>(hv);
        }
}

// ---------------- fp16 2-term tensor-core 3x3 SAME conv, 64->64, NHWC ----------------
__device__ __forceinline__ void mma_f16(float* d, uint32_t a0, uint32_t a1, uint32_t a2,
                                        uint32_t a3, uint32_t b0, uint32_t b1) {
    asm volatile("mma.sync.aligned.m16n8k16.row.col.f32.f16.f16.f32 "
                 "{%0,%1,%2,%3}, {%4,%5,%6,%7}, {%8,%9}, {%0,%1,%2,%3};"
                 : "+f"(d[0]), "+f"(d[1]), "+f"(d[2]), "+f"(d[3])
                 : "r"(a0), "r"(a1), "r"(a2), "r"(a3), "r"(b0), "r"(b1));
}
__device__ __forceinline__ void ldsm4(uint32_t& r0, uint32_t& r1, uint32_t& r2, uint32_t& r3,
                                      uint32_t addr) {
    asm volatile("ldmatrix.sync.aligned.m8n8.x4.shared.b16 {%0,%1,%2,%3}, [%4];"
                 : "=r"(r0), "=r"(r1), "=r"(r2), "=r"(r3) : "r"(addr));
}

#define IN_PITCH 36                 // words per px row (64 ci fp16 + pad)
#define PLANE    7344               // 204 px (6 rows x 34 cols) * 36 words
#define WOFF     7344               // W buffers start (words)
#define WPLANE   2304               // 64 co * 36 words
#define SMEM_WORDS (WOFF + 2 * 2 * WPLANE)          // 16560
#define SMEM_BYTES (SMEM_WORDS * 4)                 // 66240

// Warp tiling: 8 warps = 4 px-groups (32 px) x 2 co-groups (32 co).
__global__ __launch_bounds__(256, 3) void conv_mma(
        const __half* __restrict__ in,            // [B][1024][64]
        const __half* __restrict__ wh,            // [9][64][72] fp16 hi
        const __half* __restrict__ wl,            // fp16 lo
        const float* __restrict__ bias,
        const __half* res,
        __half* __restrict__ out) {
    extern __shared__ uint32_t sm[];
    uint32_t sbase = (uint32_t)__cvta_generic_to_shared(sm);
    int b = blockIdx.x, g = blockIdx.y, r0 = g * 4;
    int t = threadIdx.x, lane = t & 31, warp = t >> 5;
    int cobase = (warp >> 2) * 32;           // 2 co-groups of 32
    int pxbase = (warp & 3) * 32;            // 4 px-groups of 32

    // ---- stage input tile via cp.async: 6 rows x 34 cols, single fp16 plane ----
    const __half* ibase = in + (size_t)b * HW * 64;
    for (int idx = t; idx < 1632; idx += 256) {          // 204 px * 8 chunks
        int pxt = idx >> 3, ck = idx & 7;
        int rt = pxt / 34, ct = pxt % 34;
        int gr = r0 - 1 + rt, gc = ct - 1;
        int ok = ((unsigned)gr < 32u) && ((unsigned)gc < 32u);
        const char* src = reinterpret_cast<const char*>(
            ibase + (ok ? ((size_t)(gr * 32 + gc)) * 64 + ck * 8 : 0));
        uint32_t dst = (uint32_t)__cvta_generic_to_shared(sm + pxt * IN_PITCH + ck * 4);
        int sz = ok ? 16 : 0;
        asm volatile("cp.async.ca.shared.global [%0], [%1], 16, %2;"
                     :: "r"(dst), "l"(src), "r"(sz));
    }

    // ---- cp.async weight staging, per shift, double buffered (hi+lo planes) ----
    auto issueW = [&](int s, int buf) {
        for (int c = t; c < 1152; c += 256) {            // 2 planes * 576 16B chunks
            int plane = (c >= 576) ? 1 : 0;
            int cc = c - plane * 576;
            const char* src = reinterpret_cast<const char*>(plane ? wl : wh)
                              + (size_t)s * 9216 + cc * 16;
            uint32_t dst = (uint32_t)__cvta_generic_to_shared(
                sm + WOFF + buf * (2 * WPLANE) + plane * WPLANE + cc * 4);
            asm volatile("cp.async.ca.shared.global [%0], [%1], 16;" :: "r"(dst), "l"(src));
        }
        asm volatile("cp.async.commit_group;" ::: "memory");
    };
    issueW(0, 0);

    // ---- accumulators ----
    float acc[2][4][4];
    #pragma unroll
    for (int mt = 0; mt < 2; mt++) {
        float bv0 = bias[cobase + mt * 16 + (lane >> 2)];
        float bv1 = bias[cobase + mt * 16 + (lane >> 2) + 8];
        #pragma unroll
        for (int j = 0; j < 4; j++) {
            acc[mt][j][0] = bv0; acc[mt][j][1] = bv0;
            acc[mt][j][2] = bv1; acc[mt][j][3] = bv1;
        }
    }

    // ---- ldmatrix per-lane word offsets ----
    int a_mhalf = (lane >> 3) & 1, a_khalf = lane >> 4, a_row = lane & 7;
    int aoff[2];
    #pragma unroll
    for (int mt = 0; mt < 2; mt++)
        aoff[mt] = (cobase + mt * 16 + a_mhalf * 8 + a_row) * IN_PITCH + a_khalf * 4;
    int b_pxg = lane >> 4, b_khalf = (lane >> 3) & 1, b_row = lane & 7;
    int boff[2];
    #pragma unroll
    for (int jp = 0; jp < 2; jp++) {
        int p = pxbase + jp * 16 + b_pxg * 8 + b_row;
        int rr = p >> 5, cc = p & 31;
        boff[jp] = (rr * 34 + cc) * IN_PITCH + b_khalf * 4;
    }

    // ---- main loop over 9 shifts ----
    for (int s = 0; s < 9; s++) {
        int buf = s & 1;
        asm volatile("cp.async.wait_group 0;" ::: "memory");
        __syncthreads();
        if (s < 8) issueW(s + 1, buf ^ 1);
        int ky = s / 3, kx = s - 3 * ky;
        int soff = (ky * 34 + kx) * IN_PITCH;
        uint32_t whB = sbase + (WOFF + buf * (2 * WPLANE)) * 4;
        uint32_t wlB = whB + WPLANE * 4;
        uint32_t ihB = sbase + soff * 4;
        #pragma unroll
        for (int q = 0; q < 4; q++) {
            uint32_t ah[2][4], al[2][4], bh[2][4];
            #pragma unroll
            for (int mt = 0; mt < 2; mt++) {
                ldsm4(ah[mt][0], ah[mt][1], ah[mt][2], ah[mt][3],
                      whB + (aoff[mt] + q * 8) * 4);
                ldsm4(al[mt][0], al[mt][1], al[mt][2], al[mt][3],
                      wlB + (aoff[mt] + q * 8) * 4);
            }
            #pragma unroll
            for (int jp = 0; jp < 2; jp++)
                ldsm4(bh[jp][0], bh[jp][1], bh[jp][2], bh[jp][3],
                      ihB + (boff[jp] + q * 8) * 4);
            // term-major: Wh*A then Wl*A (reuse distance 8, shared B frags)
            #pragma unroll
            for (int mt = 0; mt < 2; mt++)
                #pragma unroll
                for (int j = 0; j < 4; j++) {
                    int jp = j >> 1, hf = (j & 1) * 2;
                    mma_f16(acc[mt][j], ah[mt][0], ah[mt][1], ah[mt][2], ah[mt][3],
                            bh[jp][hf], bh[jp][hf + 1]);
                }
            #pragma unroll
            for (int mt = 0; mt < 2; mt++)
                #pragma unroll
                for (int j = 0; j < 4; j++) {
                    int jp = j >> 1, hf = (j & 1) * 2;
                    mma_f16(acc[mt][j], al[mt][0], al[mt][1], al[mt][2], al[mt][3],
                            bh[jp][hf], bh[jp][hf + 1]);
                }
        }
    }

    // ---- epilogue: transpose through smem (fp32, pitch 68), then coalesced out ----
    float* smf = reinterpret_cast<float*>(sm);
    __syncthreads();
    {
        #pragma unroll
        for (int mt = 0; mt < 2; mt++) {
            int col = cobase + mt * 16 + (lane >> 2);
            #pragma unroll
            for (int j = 0; j < 4; j++) {
                int p0 = pxbase + j * 8 + (lane & 3) * 2;
                smf[p0 * 68 + col]            = acc[mt][j][0];
                smf[(p0 + 1) * 68 + col]      = acc[mt][j][1];
                smf[p0 * 68 + col + 8]        = acc[mt][j][2];
                smf[(p0 + 1) * 68 + col + 8]  = acc[mt][j][3];
            }
        }
    }
    __syncthreads();
    size_t obase = ((size_t)b * HW + g * 128) * 64;
    for (int idx = t; idx < 2048; idx += 256) {          // 128 px * 16 chunks of 4 co
        int px = idx >> 4, ck = idx & 15;
        float4 v = *reinterpret_cast<const float4*>(smf + px * 68 + ck * 4);
        size_t go = obase + (size_t)px * 64 + ck * 4;
        if (res) {
            uint2 rr = *reinterpret_cast<const uint2*>(res + go);
            const __half2* r2p = reinterpret_cast<const __half2*>(&rr);
            float2 a0 = __half22float2(r2p[0]), a1 = __half22float2(r2p[1]);
            v.x += a0.x; v.y += a0.y; v.z += a1.x; v.w += a1.y;
        }
        v.x = fmaxf(v.x, 0.f); v.y = fmaxf(v.y, 0.f);
        v.z = fmaxf(v.z, 0.f); v.w = fmaxf(v.w, 0.f);
        __half h[4];
        h[0] = __float2half(v.x); h[1] = __float2half(v.y);
        h[2] = __float2half(v.z); h[3] = __float2half(v.w);
        *reinterpret_cast<uint2*>(out + go) = *reinterpret_cast<uint2*>(h);
    }
}

// ---------------- GAP over fp16 NHWC ----------------
__global__ void gap_nhwc(const __half* __restrict__ in, float* __restrict__ gap) {
    __shared__ float part[4][64];
    int b = blockIdx.x, t = threadIdx.x, ci = t & 63, q = t >> 6;
    const __half* hb = in + (size_t)b * HW * 64;
    float s = 0.0f;
    for (int px = q * 256; px < q * 256 + 256; px++)
        s += __half2float(hb[(size_t)px * 64 + ci]);
    part[q][ci] = s;
    __syncthreads();
    if (t < 64)
        gap[b * 64 + t] = (part[0][t] + part[1][t] + part[2][t] + part[3][t]) * (1.0f / 1024.0f);
}

// ---------------- resnet FC + masked merge into d_out ----------------
__global__ void fc_merge(const float* __restrict__ gap, const float* __restrict__ rfc,
                         const float* __restrict__ rfb, const int* __restrict__ flag,
                         float* out) {
    __shared__ float sg[64];
    int b = blockIdx.x, t = threadIdx.x;
    sg[t] = gap[b * 64 + t];
    __syncthreads();
    if (t < 10) {
        float a = rfb[t];
        #pragma unroll
        for (int k = 0; k < 64; k++) a = fmaf(sg[k], rfc[k * 10 + t], a);
        if (flag[b]) out[(size_t)b * 10 + t] = a;
    }
}

// ---------------- launcher ----------------
extern "C" void kernel_launch(void* const* d_in, const int* in_sizes, int n_in,
                              void* d_out, int out_size) {
    const float* x    = (const float*)d_in[0];
    const float* thr  = (const float*)d_in[1];
    const int*   lab  = (const int*)d_in[2];
    const float* lw1  = (const float*)d_in[3];
    const float* lb1  = (const float*)d_in[4];
    const float* lw2  = (const float*)d_in[5];
    const float* lb2  = (const float*)d_in[6];
    const float* lfc1 = (const float*)d_in[7];
    const float* lfb1 = (const float*)d_in[8];
    const float* lfc2 = (const float*)d_in[9];
    const float* lfb2 = (const float*)d_in[10];
    const float* lfc3 = (const float*)d_in[11];
    const float* lfb3 = (const float*)d_in[12];
    const float* rw0  = (const float*)d_in[13];
    const float* rb0  = (const float*)d_in[14];
    const float* rw1a = (const float*)d_in[15];
    const float* rb1a = (const float*)d_in[16];
    const float* rw1b = (const float*)d_in[17];
    const float* rb1b = (const float*)d_in[18];
    const float* rw2a = (const float*)d_in[19];
    const float* rb2a = (const float*)d_in[20];
    const float* rw2b = (const float*)d_in[21];
    const float* rb2b = (const float*)d_in[22];
    const float* rfc  = (const float*)d_in[23];
    const float* rfb  = (const float*)d_in[24];

    float* out  = (float*)d_out;
    float* conf = out + BATCH * 10;

    __half *H, *R, *Wh, *Wl;
    float *gapb; int* flag;
    cudaGetSymbolAddress((void**)&H,    g_H);
    cudaGetSymbolAddress((void**)&R,    g_R);
    cudaGetSymbolAddress((void**)&Wh,   g_Wh);
    cudaGetSymbolAddress((void**)&Wl,   g_Wl);
    cudaGetSymbolAddress((void**)&gapb, g_gap);
    cudaGetSymbolAddress((void**)&flag, g_flag);

    cudaFuncSetAttribute(conv_mma, cudaFuncAttributeMaxDynamicSharedMemorySize, SMEM_BYTES);

    const int WL = 9 * 64 * 72;
    prep_w<<<(WL + 255) / 256, 256>>>(rw1a, Wh + 0 * WL, Wl + 0 * WL);
    prep_w<<<(WL + 255) / 256, 256>>>(rw1b, Wh + 1 * WL, Wl + 1 * WL);
    prep_w<<<(WL + 255) / 256, 256>>>(rw2a, Wh + 2 * WL, Wl + 2 * WL);
    prep_w<<<(WL + 255) / 256, 256>>>(rw2b, Wh + 3 * WL, Wl + 3 * WL);

    zero_conf<<<1, 128>>>(conf);

    // LeNet branch (fp32 exact)
    lenet_all<<<BATCH, 256>>>(x, lw1, lb1, lw2, lb2, lfc1, lfb1, lfc2, lfb2,
                              lfc3, lfb3, thr, lab, out, conf, flag);

    // ResNet branch (fp16 NHWC activations, 2-term fp16 weights)
    dim3 g0(BATCH, 4);
    conv0_k<<<g0, 256>>>(x, rw0, rb0, H);
    dim3 g(BATCH, 8);
    conv_mma<<<g, 256, SMEM_BYTES>>>(H, Wh + 0 * WL, Wl + 0 * WL, rb1a, nullptr, R);
    conv_mma<<<g, 256, SMEM_BYTES>>>(R, Wh + 1 * WL, Wl + 1 * WL, rb1b, H,       H);
    conv_mma<<<g, 256, SMEM_BYTES>>>(H, Wh + 2 * WL, Wl + 2 * WL, rb2a, nullptr, R);
    conv_mma<<<g, 256, SMEM_BYTES>>>(R, Wh + 3 * WL, Wl + 3 * WL, rb2b, H,       H);

    gap_nhwc<<<BATCH, 256>>>(H, gapb);
    fc_merge<<<BATCH, 64>>>(gapb, rfc, rfb, flag, out);
}

// round 13
// speedup vs baseline: 2.1601x; 1.4394x over previous
#include <cuda_runtime.h>
#include <cuda_fp16.h>
#include <cstdint>
#include <cstddef>

#define BATCH 1024
#define HW 1024   // 32*32

// ---------------- scratch (device globals; no allocs allowed) ----------------
__device__ __half g_H[(size_t)BATCH * HW * 64];   // 128 MB, fp16 NHWC activations
__device__ __half g_R[(size_t)BATCH * HW * 64];
__device__ __half g_W[4 * 9 * 64 * 72];           // fp16 weights (single term)
__device__ float g_gap[BATCH * 64];
__device__ int   g_flag[BATCH];

// ---------------- misc ----------------
__global__ void zero_conf(float* conf) {
    int t = threadIdx.x;
    if (t < 100) conf[t] = 0.0f;
}

// weight prep: OIHW fp32 [64][64][3][3] -> [s=9][co=64][ci pad 72] fp16
__global__ void prep_w(const float* __restrict__ w, __half* __restrict__ wo) {
    int idx = blockIdx.x * 256 + threadIdx.x;          // 9*64*72 = 41472
    if (idx >= 9 * 64 * 72) return;
    int s = idx / (64 * 72), rem = idx % (64 * 72), co = rem / 72, ci = rem % 72;
    float v = 0.0f;
    if (ci < 64) v = w[(co * 64 + ci) * 9 + s];
    wo[idx] = __float2half(v);
}

// ---------------- fused LeNet (fp32 exact) ----------------
__global__ __launch_bounds__(256) void lenet_all(
        const float* __restrict__ x, const float* __restrict__ w1, const float* __restrict__ b1,
        const float* __restrict__ w2, const float* __restrict__ b2,
        const float* __restrict__ fc1w, const float* __restrict__ fc1b,
        const float* __restrict__ fc2w, const float* __restrict__ fc2b,
        const float* __restrict__ fc3w, const float* __restrict__ fc3b,
        const float* __restrict__ thr_p, const int* __restrict__ labels,
        float* __restrict__ lenout, float* conf, int* __restrict__ flag) {
    __shared__ float sx[3 * 32 * 32];
    __shared__ float sw[2400];
    __shared__ float p1[1176];
    __shared__ float p2[400];
    __shared__ float h1[120];
    __shared__ float h2[84];
    __shared__ float lg[10];
    __shared__ float sb[16];
    int bid = blockIdx.x, t = threadIdx.x;
    const float* xb = x + (size_t)bid * 3072;
    for (int i = t; i < 3072; i += 256) sx[i] = xb[i];
    for (int i = t; i < 450; i += 256) sw[i] = w1[i];
    if (t < 6) sb[t] = b1[t];
    __syncthreads();
    for (int idx = t; idx < 6 * 14 * 14; idx += 256) {
        int c = idx / 196, py = (idx / 14) % 14, px = idx % 14;
        float m = -1e30f;
        #pragma unroll
        for (int dy = 0; dy < 2; dy++)
            #pragma unroll
            for (int dx = 0; dx < 2; dx++) {
                int y = 2 * py + dy, x0 = 2 * px + dx;
                float a = sb[c];
                for (int ci = 0; ci < 3; ci++)
                    #pragma unroll
                    for (int ky = 0; ky < 5; ky++)
                        #pragma unroll
                        for (int kx = 0; kx < 5; kx++)
                            a = fmaf(sx[ci * 1024 + (y + ky) * 32 + (x0 + kx)],
                                     sw[(c * 3 + ci) * 25 + ky * 5 + kx], a);
                m = fmaxf(m, a);
            }
        p1[idx] = fmaxf(m, 0.0f);
    }
    __syncthreads();
    for (int i = t; i < 2400; i += 256) sw[i] = w2[i];
    if (t < 16) sb[t] = b2[t];
    __syncthreads();
    for (int idx = t; idx < 400; idx += 256) {
        int c = idx / 25, py = (idx / 5) % 5, px = idx % 5;
        float m = -1e30f;
        #pragma unroll
        for (int dy = 0; dy < 2; dy++)
            #pragma unroll
            for (int dx = 0; dx < 2; dx++) {
                int y = 2 * py + dy, x0 = 2 * px + dx;
                float a = sb[c];
                for (int ci = 0; ci < 6; ci++)
                    #pragma unroll
                    for (int ky = 0; ky < 5; ky++)
                        #pragma unroll
                        for (int kx = 0; kx < 5; kx++)
                            a = fmaf(p1[ci * 196 + (y + ky) * 14 + (x0 + kx)],
                                     sw[(c * 6 + ci) * 25 + ky * 5 + kx], a);
                m = fmaxf(m, a);
            }
        p2[idx] = fmaxf(m, 0.0f);
    }
    __syncthreads();
    if (t < 120) {
        float a = fc1b[t];
        for (int k = 0; k < 400; k++) a = fmaf(p2[k], fc1w[k * 120 + t], a);
        h1[t] = fmaxf(a, 0.0f);
    }
    __syncthreads();
    if (t < 84) {
        float a = fc2b[t];
        for (int k = 0; k < 120; k++) a = fmaf(h1[k], fc2w[k * 84 + t], a);
        h2[t] = fmaxf(a, 0.0f);
    }
    __syncthreads();
    if (t < 10) {
        float a = fc3b[t];
        for (int k = 0; k < 84; k++) a = fmaf(h2[k], fc3w[k * 10 + t], a);
        lg[t] = a;
        lenout[(size_t)bid * 10 + t] = a;
    }
    __syncthreads();
    if (t == 0) {
        float m = lg[0]; int am = 0;
        #pragma unroll
        for (int i = 1; i < 10; i++) if (lg[i] > m) { m = lg[i]; am = i; }
        float p[10]; float s = 0.0f;
        #pragma unroll
        for (int i = 0; i < 10; i++) { p[i] = expf(lg[i] - m); s += p[i]; }
        float inv = 1.0f / s;
        float p0 = -1.0f, pp1 = -1.0f;
        #pragma unroll
        for (int i = 0; i < 10; i++) {
            float v = p[i] * inv;
            if (v > p0) { pp1 = p0; p0 = v; } else if (v > pp1) { pp1 = v; }
        }
        flag[bid] = ((p0 - pp1) <= thr_p[0]) ? 1 : 0;
        atomicAdd(&conf[labels[bid] * 10 + am], 1.0f);
    }
}

// ---------------- ResNet conv0 (3->64, fp32 direct), fp16 NHWC out + ReLU ----------------
__global__ __launch_bounds__(256, 2) void conv0_k(const float* __restrict__ x,
        const float* __restrict__ w, const float* __restrict__ bias,
        __half* __restrict__ out) {
    __shared__ __align__(16) float s_in[3 * 10 * 36];
    __shared__ float s_w[3 * 64 * 9];
    int b = blockIdx.x, row0 = blockIdx.y * 8;
    int t = threadIdx.x, warp = t >> 5, lane = t & 31;
    int r2 = lane >> 3, colg = lane & 7, cob = warp * 8;

    float acc[2][4][8];
    #pragma unroll
    for (int oc = 0; oc < 8; oc++) {
        float bv = bias[cob + oc];
        #pragma unroll
        for (int rr = 0; rr < 2; rr++)
            #pragma unroll
            for (int cc = 0; cc < 4; cc++) acc[rr][cc][oc] = bv;
    }
    const float* inb = x + (size_t)b * 3 * HW;
    for (int idx = t; idx < 3 * 340; idx += 256) {
        int kc = idx / 340, rem = idx % 340, r = rem / 34, c = rem % 34;
        int gr = row0 - 1 + r, gc = c - 1;
        float v = 0.0f;
        if ((unsigned)gr < 32u && (unsigned)gc < 32u)
            v = inb[(size_t)kc * HW + gr * 32 + gc];
        s_in[kc * 360 + r * 36 + c] = v;
    }
    for (int idx = t; idx < 3 * 576; idx += 256) {
        int kc = idx / 576, rem = idx % 576, co = rem / 9, k = rem % 9;
        s_w[idx] = w[((size_t)co * 3 + kc) * 9 + k];
    }
    __syncthreads();
    #pragma unroll
    for (int kc = 0; kc < 3; kc++) {
        float xin[4][6];
        const float* sbase = s_in + kc * 360 + (r2 * 2) * 36 + colg * 4;
        #pragma unroll
        for (int r = 0; r < 4; r++) {
            float4 a = *reinterpret_cast<const float4*>(sbase + r * 36);
            float2 bv = *reinterpret_cast<const float2*>(sbase + r * 36 + 4);
            xin[r][0] = a.x; xin[r][1] = a.y; xin[r][2] = a.z; xin[r][3] = a.w;
            xin[r][4] = bv.x; xin[r][5] = bv.y;
        }
        const float* wp = s_w + kc * 576 + cob * 9;
        #pragma unroll
        for (int oc = 0; oc < 8; oc++) {
            float w0 = wp[oc * 9], w1 = wp[oc * 9 + 1], w2 = wp[oc * 9 + 2];
            float w3 = wp[oc * 9 + 3], w4 = wp[oc * 9 + 4], w5 = wp[oc * 9 + 5];
            float w6 = wp[oc * 9 + 6], w7 = wp[oc * 9 + 7], w8 = wp[oc * 9 + 8];
            #pragma unroll
            for (int rr = 0; rr < 2; rr++)
                #pragma unroll
                for (int cc = 0; cc < 4; cc++) {
                    float a = acc[rr][cc][oc];
                    a = fmaf(xin[rr][cc],     w0, a);
                    a = fmaf(xin[rr][cc + 1], w1, a);
                    a = fmaf(xin[rr][cc + 2], w2, a);
                    a = fmaf(xin[rr + 1][cc],     w3, a);
                    a = fmaf(xin[rr + 1][cc + 1], w4, a);
                    a = fmaf(xin[rr + 1][cc + 2], w5, a);
                    a = fmaf(xin[rr + 2][cc],     w6, a);
                    a = fmaf(xin[rr + 2][cc + 1], w7, a);
                    a = fmaf(xin[rr + 2][cc + 2], w8, a);
                    acc[rr][cc][oc] = a;
                }
        }
    }
    size_t ob = (size_t)b * HW * 64;
    #pragma unroll
    for (int rr = 0; rr < 2; rr++)
        #pragma unroll
        for (int cc = 0; cc < 4; cc++) {
            int px = (row0 + r2 * 2 + rr) * 32 + colg * 4 + cc;
            __half hv[8];
            #pragma unroll
            for (int oc = 0; oc < 8; oc++)
                hv[oc] = __float2half(fmaxf(acc[rr][cc][oc], 0.f));
            *reinterpret_cast<uint4*>(out + ob + (size_t)px * 64 + cob) =
                *reinterpret_cast<uint4*>(hv);
        }
}

// ---------------- fp16 1-term tensor-core 3x3 SAME conv, 64->64, NHWC ----------------
__device__ __forceinline__ void mma_f16(float* d, uint32_t a0, uint32_t a1, uint32_t a2,
                                        uint32_t a3, uint32_t b0, uint32_t b1) {
    asm volatile("mma.sync.aligned.m16n8k16.row.col.f32.f16.f16.f32 "
                 "{%0,%1,%2,%3}, {%4,%5,%6,%7}, {%8,%9}, {%0,%1,%2,%3};"
                 : "+f"(d[0]), "+f"(d[1]), "+f"(d[2]), "+f"(d[3])
                 : "r"(a0), "r"(a1), "r"(a2), "r"(a3), "r"(b0), "r"(b1));
}
__device__ __forceinline__ void ldsm4(uint32_t& r0, uint32_t& r1, uint32_t& r2, uint32_t& r3,
                                      uint32_t addr) {
    asm volatile("ldmatrix.sync.aligned.m8n8.x4.shared.b16 {%0,%1,%2,%3}, [%4];"
                 : "=r"(r0), "=r"(r1), "=r"(r2), "=r"(r3) : "r"(addr));
}

#define IN_PITCH 36                 // words per px row (64 ci fp16 + pad)
#define PLANE    7344               // 204 px (6 rows x 34 cols) * 36 words
#define WOFF     7344               // W buffers start (words)
#define WPLANE   2304               // 64 co * 36 words
#define SMEM_WORDS (WOFF + 2 * WPLANE)              // 11952
#define SMEM_BYTES (SMEM_WORDS * 4)                 // 47808

// Warp tiling: 8 warps = 4 px-groups (32 px) x 2 co-groups (32 co).
__global__ __launch_bounds__(256, 3) void conv_mma(
        const __half* __restrict__ in,            // [B][1024][64]
        const __half* __restrict__ w,             // [9][64][72] fp16
        const float* __restrict__ bias,
        const __half* res,
        __half* __restrict__ out) {
    extern __shared__ uint32_t sm[];
    uint32_t sbase = (uint32_t)__cvta_generic_to_shared(sm);
    int b = blockIdx.x, g = blockIdx.y, r0 = g * 4;
    int t = threadIdx.x, lane = t & 31, warp = t >> 5;
    int cobase = (warp >> 2) * 32;           // 2 co-groups of 32
    int pxbase = (warp & 3) * 32;            // 4 px-groups of 32

    // ---- stage input tile via cp.async: 6 rows x 34 cols, single fp16 plane ----
    const __half* ibase = in + (size_t)b * HW * 64;
    for (int idx = t; idx < 1632; idx += 256) {          // 204 px * 8 chunks
        int pxt = idx >> 3, ck = idx & 7;
        int rt = pxt / 34, ct = pxt % 34;
        int gr = r0 - 1 + rt, gc = ct - 1;
        int ok = ((unsigned)gr < 32u) && ((unsigned)gc < 32u);
        const char* src = reinterpret_cast<const char*>(
            ibase + (ok ? ((size_t)(gr * 32 + gc)) * 64 + ck * 8 : 0));
        uint32_t dst = (uint32_t)__cvta_generic_to_shared(sm + pxt * IN_PITCH + ck * 4);
        int sz = ok ? 16 : 0;
        asm volatile("cp.async.ca.shared.global [%0], [%1], 16, %2;"
                     :: "r"(dst), "l"(src), "r"(sz));
    }

    // ---- cp.async weight staging, per shift, double buffered (single plane) ----
    auto issueW = [&](int s, int buf) {
        for (int c = t; c < 576; c += 256) {             // 576 16B chunks
            const char* src = reinterpret_cast<const char*>(w) + (size_t)s * 9216 + c * 16;
            uint32_t dst = (uint32_t)__cvta_generic_to_shared(
                sm + WOFF + buf * WPLANE + c * 4);
            asm volatile("cp.async.ca.shared.global [%0], [%1], 16;" :: "r"(dst), "l"(src));
        }
        asm volatile("cp.async.commit_group;" ::: "memory");
    };
    issueW(0, 0);

    // ---- accumulators ----
    float acc[2][4][4];
    #pragma unroll
    for (int mt = 0; mt < 2; mt++) {
        float bv0 = bias[cobase + mt * 16 + (lane >> 2)];
        float bv1 = bias[cobase + mt * 16 + (lane >> 2) + 8];
        #pragma unroll
        for (int j = 0; j < 4; j++) {
            acc[mt][j][0] = bv0; acc[mt][j][1] = bv0;
            acc[mt][j][2] = bv1; acc[mt][j][3] = bv1;
        }
    }

    // ---- ldmatrix per-lane word offsets ----
    int a_mhalf = (lane >> 3) & 1, a_khalf = lane >> 4, a_row = lane & 7;
    int aoff[2];
    #pragma unroll
    for (int mt = 0; mt < 2; mt++)
        aoff[mt] = (cobase + mt * 16 + a_mhalf * 8 + a_row) * IN_PITCH + a_khalf * 4;
    int b_pxg = lane >> 4, b_khalf = (lane >> 3) & 1, b_row = lane & 7;
    int boff[2];
    #pragma unroll
    for (int jp = 0; jp < 2; jp++) {
        int p = pxbase + jp * 16 + b_pxg * 8 + b_row;
        int rr = p >> 5, cc = p & 31;
        boff[jp] = (rr * 34 + cc) * IN_PITCH + b_khalf * 4;
    }

    // ---- main loop over 9 shifts ----
    for (int s = 0; s < 9; s++) {
        int buf = s & 1;
        asm volatile("cp.async.wait_group 0;" ::: "memory");
        __syncthreads();
        if (s < 8) issueW(s + 1, buf ^ 1);
        int ky = s / 3, kx = s - 3 * ky;
        int soff = (ky * 34 + kx) * IN_PITCH;
        uint32_t whB = sbase + (WOFF + buf * WPLANE) * 4;
        uint32_t ihB = sbase + soff * 4;
        #pragma unroll
        for (int q = 0; q < 4; q++) {
            uint32_t ah[2][4], bh[2][4];
            #pragma unroll
            for (int mt = 0; mt < 2; mt++)
                ldsm4(ah[mt][0], ah[mt][1], ah[mt][2], ah[mt][3],
                      whB + (aoff[mt] + q * 8) * 4);
            #pragma unroll
            for (int jp = 0; jp < 2; jp++)
                ldsm4(bh[jp][0], bh[jp][1], bh[jp][2], bh[jp][3],
                      ihB + (boff[jp] + q * 8) * 4);
            #pragma unroll
            for (int mt = 0; mt < 2; mt++)
                #pragma unroll
                for (int j = 0; j < 4; j++) {
                    int jp = j >> 1, hf = (j & 1) * 2;
                    mma_f16(acc[mt][j], ah[mt][0], ah[mt][1], ah[mt][2], ah[mt][3],
                            bh[jp][hf], bh[jp][hf + 1]);
                }
        }
    }

    // ---- epilogue: transpose through smem (fp32, pitch 68), then coalesced out ----
    float* smf = reinterpret_cast<float*>(sm);
    __syncthreads();
    {
        #pragma unroll
        for (int mt = 0; mt < 2; mt++) {
            int col = cobase + mt * 16 + (lane >> 2);
            #pragma unroll
            for (int j = 0; j < 4; j++) {
                int p0 = pxbase + j * 8 + (lane & 3) * 2;
                smf[p0 * 68 + col]            = acc[mt][j][0];
                smf[(p0 + 1) * 68 + col]      = acc[mt][j][1];
                smf[p0 * 68 + col + 8]        = acc[mt][j][2];
                smf[(p0 + 1) * 68 + col + 8]  = acc[mt][j][3];
            }
        }
    }
    __syncthreads();
    size_t obase = ((size_t)b * HW + g * 128) * 64;
    for (int idx = t; idx < 2048; idx += 256) {          // 128 px * 16 chunks of 4 co
        int px = idx >> 4, ck = idx & 15;
        float4 v = *reinterpret_cast<const float4*>(smf + px * 68 + ck * 4);
        size_t go = obase + (size_t)px * 64 + ck * 4;
        if (res) {
            uint2 rr = *reinterpret_cast<const uint2*>(res + go);
            const __half2* r2p = reinterpret_cast<const __half2*>(&rr);
            float2 a0 = __half22float2(r2p[0]), a1 = __half22float2(r2p[1]);
            v.x += a0.x; v.y += a0.y; v.z += a1.x; v.w += a1.y;
        }
        v.x = fmaxf(v.x, 0.f); v.y = fmaxf(v.y, 0.f);
        v.z = fmaxf(v.z, 0.f); v.w = fmaxf(v.w, 0.f);
        __half h[4];
        h[0] = __float2half(v.x); h[1] = __float2half(v.y);
        h[2] = __float2half(v.z); h[3] = __float2half(v.w);
        *reinterpret_cast<uint2*>(out + go) = *reinterpret_cast<uint2*>(h);
    }
}

// ---------------- GAP over fp16 NHWC ----------------
__global__ void gap_nhwc(const __half* __restrict__ in, float* __restrict__ gap) {
    __shared__ float part[4][64];
    int b = blockIdx.x, t = threadIdx.x, ci = t & 63, q = t >> 6;
    const __half* hb = in + (size_t)b * HW * 64;
    float s = 0.0f;
    for (int px = q * 256; px < q * 256 + 256; px++)
        s += __half2float(hb[(size_t)px * 64 + ci]);
    part[q][ci] = s;
    __syncthreads();
    if (t < 64)
        gap[b * 64 + t] = (part[0][t] + part[1][t] + part[2][t] + part[3][t]) * (1.0f / 1024.0f);
}

// ---------------- resnet FC + masked merge into d_out ----------------
__global__ void fc_merge(const float* __restrict__ gap, const float* __restrict__ rfc,
                         const float* __restrict__ rfb, const int* __restrict__ flag,
                         float* out) {
    __shared__ float sg[64];
    int b = blockIdx.x, t = threadIdx.x;
    sg[t] = gap[b * 64 + t];
    __syncthreads();
    if (t < 10) {
        float a = rfb[t];
        #pragma unroll
        for (int k = 0; k < 64; k++) a = fmaf(sg[k], rfc[k * 10 + t], a);
        if (flag[b]) out[(size_t)b * 10 + t] = a;
    }
}

// ---------------- launcher ----------------
extern "C" void kernel_launch(void* const* d_in, const int* in_sizes, int n_in,
                              void* d_out, int out_size) {
    const float* x    = (const float*)d_in[0];
    const float* thr  = (const float*)d_in[1];
    const int*   lab  = (const int*)d_in[2];
    const float* lw1  = (const float*)d_in[3];
    const float* lb1  = (const float*)d_in[4];
    const float* lw2  = (const float*)d_in[5];
    const float* lb2  = (const float*)d_in[6];
    const float* lfc1 = (const float*)d_in[7];
    const float* lfb1 = (const float*)d_in[8];
    const float* lfc2 = (const float*)d_in[9];
    const float* lfb2 = (const float*)d_in[10];
    const float* lfc3 = (const float*)d_in[11];
    const float* lfb3 = (const float*)d_in[12];
    const float* rw0  = (const float*)d_in[13];
    const float* rb0  = (const float*)d_in[14];
    const float* rw1a = (const float*)d_in[15];
    const float* rb1a = (const float*)d_in[16];
    const float* rw1b = (const float*)d_in[17];
    const float* rb1b = (const float*)d_in[18];
    const float* rw2a = (const float*)d_in[19];
    const float* rb2a = (const float*)d_in[20];
    const float* rw2b = (const float*)d_in[21];
    const float* rb2b = (const float*)d_in[22];
    const float* rfc  = (const float*)d_in[23];
    const float* rfb  = (const float*)d_in[24];

    float* out  = (float*)d_out;
    float* conf = out + BATCH * 10;

    __half *H, *R, *W;
    float *gapb; int* flag;
    cudaGetSymbolAddress((void**)&H,    g_H);
    cudaGetSymbolAddress((void**)&R,    g_R);
    cudaGetSymbolAddress((void**)&W,    g_W);
    cudaGetSymbolAddress((void**)&gapb, g_gap);
    cudaGetSymbolAddress((void**)&flag, g_flag);

    cudaFuncSetAttribute(conv_mma, cudaFuncAttributeMaxDynamicSharedMemorySize, SMEM_BYTES);

    const int WL = 9 * 64 * 72;
    prep_w<<<(WL + 255) / 256, 256>>>(rw1a, W + 0 * WL);
    prep_w<<<(WL + 255) / 256, 256>>>(rw1b, W + 1 * WL);
    prep_w<<<(WL + 255) / 256, 256>>>(rw2a, W + 2 * WL);
    prep_w<<<(WL + 255) / 256, 256>>>(rw2b, W + 3 * WL);

    zero_conf<<<1, 128>>>(conf);

    // LeNet branch (fp32 exact)
    lenet_all<<<BATCH, 256>>>(x, lw1, lb1, lw2, lb2, lfc1, lfb1, lfc2, lfb2,
                              lfc3, lfb3, thr, lab, out, conf, flag);

    // ResNet branch (fp16 NHWC activations, single-term fp16 weights)
    dim3 g0(BATCH, 4);
    conv0_k<<<g0, 256>>>(x, rw0, rb0, H);
    dim3 g(BATCH, 8);
    conv_mma<<<g, 256, SMEM_BYTES>>>(H, W + 0 * WL, rb1a, nullptr, R);
    conv_mma<<<g, 256, SMEM_BYTES>>>(R, W + 1 * WL, rb1b, H,       H);
    conv_mma<<<g, 256, SMEM_BYTES>>>(H, W + 2 * WL, rb2a, nullptr, R);
    conv_mma<<<g, 256, SMEM_BYTES>>>(R, W + 3 * WL, rb2b, H,       H);

    gap_nhwc<<<BATCH, 256>>>(H, gapb);
    fc_merge<<<BATCH, 64>>>(gapb, rfc, rfb, flag, out);
}

// round 14
// speedup vs baseline: 2.2911x; 1.0606x over previous
#include <cuda_runtime.h>
#include <cuda_fp16.h>
#include <cstdint>
#include <cstddef>

#define BATCH 1024
#define HW 1024   // 32*32

// ---------------- scratch (device globals; no allocs allowed) ----------------
__device__ __half g_H[(size_t)BATCH * HW * 64];   // 128 MB, fp16 NHWC activations
__device__ __half g_R[(size_t)BATCH * HW * 64];
__device__ __half g_W[4 * 9 * 64 * 72];           // fp16 conv weights (single term)
__device__ __half g_W0[64 * 40];                  // conv0 im2col weights [co][pitch 40 halves]
__device__ float g_gap[BATCH * 64];
__device__ int   g_flag[BATCH];

// ---------------- misc ----------------
__global__ void zero_conf(float* conf) {
    int t = threadIdx.x;
    if (t < 100) conf[t] = 0.0f;
}

// weight prep: OIHW fp32 [64][64][3][3] -> [s=9][co=64][ci pad 72] fp16
__global__ void prep_w(const float* __restrict__ w, __half* __restrict__ wo) {
    int idx = blockIdx.x * 256 + threadIdx.x;          // 9*64*72 = 41472
    if (idx >= 9 * 64 * 72) return;
    int s = idx / (64 * 72), rem = idx % (64 * 72), co = rem / 72, ci = rem % 72;
    float v = 0.0f;
    if (ci < 64) v = w[(co * 64 + ci) * 9 + s];
    wo[idx] = __float2half(v);
}

// conv0 weight prep: [64][3][3][3] fp32 -> [co][k pad 40] fp16, k = ci*9+ky*3+kx
__global__ void prep_w0(const float* __restrict__ w, __half* __restrict__ wo) {
    int idx = blockIdx.x * 256 + threadIdx.x;          // 64*40 = 2560
    if (idx >= 64 * 40) return;
    int co = idx / 40, k = idx % 40;
    float v = (k < 27) ? w[co * 27 + k] : 0.0f;
    wo[idx] = __float2half(v);
}

// ---------------- fused LeNet (fp32 exact) + gap zeroing ----------------
__global__ __launch_bounds__(256) void lenet_all(
        const float* __restrict__ x, const float* __restrict__ w1, const float* __restrict__ b1,
        const float* __restrict__ w2, const float* __restrict__ b2,
        const float* __restrict__ fc1w, const float* __restrict__ fc1b,
        const float* __restrict__ fc2w, const float* __restrict__ fc2b,
        const float* __restrict__ fc3w, const float* __restrict__ fc3b,
        const float* __restrict__ thr_p, const int* __restrict__ labels,
        float* __restrict__ lenout, float* conf, int* __restrict__ flag,
        float* __restrict__ gapz) {
    __shared__ float sx[3 * 32 * 32];
    __shared__ float sw[2400];
    __shared__ float p1[1176];
    __shared__ float p2[400];
    __shared__ float h1[120];
    __shared__ float h2[84];
    __shared__ float lg[10];
    __shared__ float sb[16];
    int bid = blockIdx.x, t = threadIdx.x;
    if (t < 64) gapz[bid * 64 + t] = 0.0f;   // zero gap for fused GAP atomics
    const float* xb = x + (size_t)bid * 3072;
    for (int i = t; i < 3072; i += 256) sx[i] = xb[i];
    for (int i = t; i < 450; i += 256) sw[i] = w1[i];
    if (t < 6) sb[t] = b1[t];
    __syncthreads();
    for (int idx = t; idx < 6 * 14 * 14; idx += 256) {
        int c = idx / 196, py = (idx / 14) % 14, px = idx % 14;
        float m = -1e30f;
        #pragma unroll
        for (int dy = 0; dy < 2; dy++)
            #pragma unroll
            for (int dx = 0; dx < 2; dx++) {
                int y = 2 * py + dy, x0 = 2 * px + dx;
                float a = sb[c];
                for (int ci = 0; ci < 3; ci++)
                    #pragma unroll
                    for (int ky = 0; ky < 5; ky++)
                        #pragma unroll
                        for (int kx = 0; kx < 5; kx++)
                            a = fmaf(sx[ci * 1024 + (y + ky) * 32 + (x0 + kx)],
                                     sw[(c * 3 + ci) * 25 + ky * 5 + kx], a);
                m = fmaxf(m, a);
            }
        p1[idx] = fmaxf(m, 0.0f);
    }
    __syncthreads();
    for (int i = t; i < 2400; i += 256) sw[i] = w2[i];
    if (t < 16) sb[t] = b2[t];
    __syncthreads();
    for (int idx = t; idx < 400; idx += 256) {
        int c = idx / 25, py = (idx / 5) % 5, px = idx % 5;
        float m = -1e30f;
        #pragma unroll
        for (int dy = 0; dy < 2; dy++)
            #pragma unroll
            for (int dx = 0; dx < 2; dx++) {
                int y = 2 * py + dy, x0 = 2 * px + dx;
                float a = sb[c];
                for (int ci = 0; ci < 6; ci++)
                    #pragma unroll
                    for (int ky = 0; ky < 5; ky++)
                        #pragma unroll
                        for (int kx = 0; kx < 5; kx++)
                            a = fmaf(p1[ci * 196 + (y + ky) * 14 + (x0 + kx)],
                                     sw[(c * 6 + ci) * 25 + ky * 5 + kx], a);
                m = fmaxf(m, a);
            }
        p2[idx] = fmaxf(m, 0.0f);
    }
    __syncthreads();
    if (t < 120) {
        float a = fc1b[t];
        for (int k = 0; k < 400; k++) a = fmaf(p2[k], fc1w[k * 120 + t], a);
        h1[t] = fmaxf(a, 0.0f);
    }
    __syncthreads();
    if (t < 84) {
        float a = fc2b[t];
        for (int k = 0; k < 120; k++) a = fmaf(h1[k], fc2w[k * 84 + t], a);
        h2[t] = fmaxf(a, 0.0f);
    }
    __syncthreads();
    if (t < 10) {
        float a = fc3b[t];
        for (int k = 0; k < 84; k++) a = fmaf(h2[k], fc3w[k * 10 + t], a);
        lg[t] = a;
        lenout[(size_t)bid * 10 + t] = a;
    }
    __syncthreads();
    if (t == 0) {
        float m = lg[0]; int am = 0;
        #pragma unroll
        for (int i = 1; i < 10; i++) if (lg[i] > m) { m = lg[i]; am = i; }
        float p[10]; float s = 0.0f;
        #pragma unroll
        for (int i = 0; i < 10; i++) { p[i] = expf(lg[i] - m); s += p[i]; }
        float inv = 1.0f / s;
        float p0 = -1.0f, pp1 = -1.0f;
        #pragma unroll
        for (int i = 0; i < 10; i++) {
            float v = p[i] * inv;
            if (v > p0) { pp1 = p0; p0 = v; } else if (v > pp1) { pp1 = v; }
        }
        flag[bid] = ((p0 - pp1) <= thr_p[0]) ? 1 : 0;
        atomicAdd(&conf[labels[bid] * 10 + am], 1.0f);
    }
}

// ---------------- mma/ldmatrix helpers ----------------
__device__ __forceinline__ void mma_f16(float* d, uint32_t a0, uint32_t a1, uint32_t a2,
                                        uint32_t a3, uint32_t b0, uint32_t b1) {
    asm volatile("mma.sync.aligned.m16n8k16.row.col.f32.f16.f16.f32 "
                 "{%0,%1,%2,%3}, {%4,%5,%6,%7}, {%8,%9}, {%0,%1,%2,%3};"
                 : "+f"(d[0]), "+f"(d[1]), "+f"(d[2]), "+f"(d[3])
                 : "r"(a0), "r"(a1), "r"(a2), "r"(a3), "r"(b0), "r"(b1));
}
__device__ __forceinline__ void ldsm4(uint32_t& r0, uint32_t& r1, uint32_t& r2, uint32_t& r3,
                                      uint32_t addr) {
    asm volatile("ldmatrix.sync.aligned.m8n8.x4.shared.b16 {%0,%1,%2,%3}, [%4];"
                 : "=r"(r0), "=r"(r1), "=r"(r2), "=r"(r3) : "r"(addr));
}

// ---------------- conv0 as im2col fp16 GEMM: M=64co, K=32, N=256px/CTA ----------------
// smem words: [0:1080) fp32 input tile 3x10x36; [1080:2360) A 64 rows x 20w;
// [2360:7480) B 256 rows x 20w. Epilogue reuses from 0 as 256x68 fp32.
#define C0_SIN 0
#define C0_A   1080
#define C0_B   2360
#define C0_SMEM_BYTES (256 * 68 * 4)   // 69632, covers staging (29.9KB) too

__global__ __launch_bounds__(256, 2) void conv0_mma(const float* __restrict__ x,
        const __half* __restrict__ w0, const float* __restrict__ bias,
        __half* __restrict__ out) {
    extern __shared__ uint32_t sm[];
    uint32_t sbase = (uint32_t)__cvta_generic_to_shared(sm);
    float* sin = reinterpret_cast<float*>(sm + C0_SIN);
    int b = blockIdx.x, row0 = blockIdx.y * 8;
    int t = threadIdx.x, lane = t & 31, warp = t >> 5;
    int cobase = (warp >> 2) * 32;           // 2 co-groups of 32
    int pxbase = (warp & 3) * 64;            // 4 px-groups of 64

    // stage fp32 input tile (3 ci x 10 rows x 34 cols, pitch 36)
    const float* inb = x + (size_t)b * 3 * HW;
    for (int idx = t; idx < 3 * 340; idx += 256) {
        int kc = idx / 340, rem = idx % 340, r = rem / 34, c = rem % 34;
        int gr = row0 - 1 + r, gc = c - 1;
        float v = 0.0f;
        if ((unsigned)gr < 32u && (unsigned)gc < 32u)
            v = inb[(size_t)kc * HW + gr * 32 + gc];
        sin[kc * 360 + r * 36 + c] = v;
    }
    // stage A weights: 64 rows x 20 words
    for (int i = t; i < 1280; i += 256)
        sm[C0_A + i] = reinterpret_cast<const uint32_t*>(w0)[i];
    __syncthreads();

    // build B im2col: px = t, k = ci*9+ky*3+kx (27, pad 32)
    {
        int r = t >> 5, c = t & 31;
        __half hv[32];
        #pragma unroll
        for (int ci = 0; ci < 3; ci++)
            #pragma unroll
            for (int ky = 0; ky < 3; ky++)
                #pragma unroll
                for (int kx = 0; kx < 3; kx++)
                    hv[ci * 9 + ky * 3 + kx] =
                        __float2half(sin[ci * 360 + (r + ky) * 36 + (c + kx)]);
        #pragma unroll
        for (int k = 27; k < 32; k++) hv[k] = __float2half(0.0f);
        uint32_t* hw = reinterpret_cast<uint32_t*>(hv);
        #pragma unroll
        for (int wv = 0; wv < 16; wv++) sm[C0_B + t * 20 + wv] = hw[wv];
    }
    __syncthreads();

    // accumulators with bias
    float acc[2][8][4];
    #pragma unroll
    for (int mt = 0; mt < 2; mt++) {
        float bv0 = bias[cobase + mt * 16 + (lane >> 2)];
        float bv1 = bias[cobase + mt * 16 + (lane >> 2) + 8];
        #pragma unroll
        for (int j = 0; j < 8; j++) {
            acc[mt][j][0] = bv0; acc[mt][j][1] = bv0;
            acc[mt][j][2] = bv1; acc[mt][j][3] = bv1;
        }
    }
    int a_mhalf = (lane >> 3) & 1, a_khalf = lane >> 4, a_row = lane & 7;
    int b_pxg = lane >> 4, b_khalf = (lane >> 3) & 1, b_row = lane & 7;
    #pragma unroll
    for (int q = 0; q < 2; q++) {
        uint32_t ah[2][4];
        #pragma unroll
        for (int mt = 0; mt < 2; mt++) {
            int aoff = (cobase + mt * 16 + a_mhalf * 8 + a_row) * 20 + q * 8 + a_khalf * 4;
            ldsm4(ah[mt][0], ah[mt][1], ah[mt][2], ah[mt][3],
                  sbase + (C0_A + aoff) * 4);
        }
        #pragma unroll
        for (int jp = 0; jp < 4; jp++) {
            uint32_t bh[4];
            int p = pxbase + jp * 16 + b_pxg * 8 + b_row;
            int boff = p * 20 + q * 8 + b_khalf * 4;
            ldsm4(bh[0], bh[1], bh[2], bh[3], sbase + (C0_B + boff) * 4);
            #pragma unroll
            for (int sub = 0; sub < 2; sub++) {
                int j = jp * 2 + sub, hf = sub * 2;
                #pragma unroll
                for (int mt = 0; mt < 2; mt++)
                    mma_f16(acc[mt][j], ah[mt][0], ah[mt][1], ah[mt][2], ah[mt][3],
                            bh[hf], bh[hf + 1]);
            }
        }
    }

    // epilogue: transpose through smem fp32 pitch 68, relu, fp16 NHWC store
    float* smf = reinterpret_cast<float*>(sm);
    __syncthreads();
    #pragma unroll
    for (int mt = 0; mt < 2; mt++) {
        int col = cobase + mt * 16 + (lane >> 2);
        #pragma unroll
        for (int j = 0; j < 8; j++) {
            int p0 = pxbase + j * 8 + (lane & 3) * 2;
            smf[p0 * 68 + col]            = acc[mt][j][0];
            smf[(p0 + 1) * 68 + col]      = acc[mt][j][1];
            smf[p0 * 68 + col + 8]        = acc[mt][j][2];
            smf[(p0 + 1) * 68 + col + 8]  = acc[mt][j][3];
        }
    }
    __syncthreads();
    size_t obase = ((size_t)b * HW + row0 * 32) * 64;
    for (int idx = t; idx < 4096; idx += 256) {        // 256 px * 16 chunks
        int px = idx >> 4, ck = idx & 15;
        float4 v = *reinterpret_cast<const float4*>(smf + px * 68 + ck * 4);
        v.x = fmaxf(v.x, 0.f); v.y = fmaxf(v.y, 0.f);
        v.z = fmaxf(v.z, 0.f); v.w = fmaxf(v.w, 0.f);
        __half h[4];
        h[0] = __float2half(v.x); h[1] = __float2half(v.y);
        h[2] = __float2half(v.z); h[3] = __float2half(v.w);
        *reinterpret_cast<uint2*>(out + obase + (size_t)px * 64 + ck * 4) =
            *reinterpret_cast<uint2*>(h);
    }
}

// ---------------- fp16 1-term tensor-core 3x3 SAME conv, 64->64, NHWC ----------------
#define IN_PITCH 36                 // words per px row (64 ci fp16 + pad)
#define PLANE    7344               // 204 px (6 rows x 34 cols) * 36 words
#define WOFF     7344               // W buffers start (words)
#define WPLANE   2304               // 64 co * 36 words
#define SMEM_WORDS (WOFF + 2 * WPLANE)              // 11952
#define SMEM_BYTES (SMEM_WORDS * 4)                 // 47808

// Warp tiling: 8 warps = 4 px-groups (32 px) x 2 co-groups (32 co).
__global__ __launch_bounds__(256, 3) void conv_mma(
        const __half* __restrict__ in,            // [B][1024][64]
        const __half* __restrict__ w,             // [9][64][72] fp16
        const float* __restrict__ bias,
        const __half* res,
        __half* __restrict__ out,
        float* gap) {                             // non-null on last layer: fused GAP
    extern __shared__ uint32_t sm[];
    uint32_t sbase = (uint32_t)__cvta_generic_to_shared(sm);
    int b = blockIdx.x, g = blockIdx.y, r0 = g * 4;
    int t = threadIdx.x, lane = t & 31, warp = t >> 5;
    int cobase = (warp >> 2) * 32;           // 2 co-groups of 32
    int pxbase = (warp & 3) * 32;            // 4 px-groups of 32

    // ---- stage input tile via cp.async: 6 rows x 34 cols, single fp16 plane ----
    const __half* ibase = in + (size_t)b * HW * 64;
    for (int idx = t; idx < 1632; idx += 256) {          // 204 px * 8 chunks
        int pxt = idx >> 3, ck = idx & 7;
        int rt = pxt / 34, ct = pxt % 34;
        int gr = r0 - 1 + rt, gc = ct - 1;
        int ok = ((unsigned)gr < 32u) && ((unsigned)gc < 32u);
        const char* src = reinterpret_cast<const char*>(
            ibase + (ok ? ((size_t)(gr * 32 + gc)) * 64 + ck * 8 : 0));
        uint32_t dst = (uint32_t)__cvta_generic_to_shared(sm + pxt * IN_PITCH + ck * 4);
        int sz = ok ? 16 : 0;
        asm volatile("cp.async.ca.shared.global [%0], [%1], 16, %2;"
                     :: "r"(dst), "l"(src), "r"(sz));
    }

    // ---- cp.async weight staging, per shift, double buffered ----
    auto issueW = [&](int s, int buf) {
        for (int c = t; c < 576; c += 256) {
            const char* src = reinterpret_cast<const char*>(w) + (size_t)s * 9216 + c * 16;
            uint32_t dst = (uint32_t)__cvta_generic_to_shared(
                sm + WOFF + buf * WPLANE + c * 4);
            asm volatile("cp.async.ca.shared.global [%0], [%1], 16;" :: "r"(dst), "l"(src));
        }
        asm volatile("cp.async.commit_group;" ::: "memory");
    };
    issueW(0, 0);

    // ---- accumulators ----
    float acc[2][4][4];
    #pragma unroll
    for (int mt = 0; mt < 2; mt++) {
        float bv0 = bias[cobase + mt * 16 + (lane >> 2)];
        float bv1 = bias[cobase + mt * 16 + (lane >> 2) + 8];
        #pragma unroll
        for (int j = 0; j < 4; j++) {
            acc[mt][j][0] = bv0; acc[mt][j][1] = bv0;
            acc[mt][j][2] = bv1; acc[mt][j][3] = bv1;
        }
    }

    int a_mhalf = (lane >> 3) & 1, a_khalf = lane >> 4, a_row = lane & 7;
    int aoff[2];
    #pragma unroll
    for (int mt = 0; mt < 2; mt++)
        aoff[mt] = (cobase + mt * 16 + a_mhalf * 8 + a_row) * IN_PITCH + a_khalf * 4;
    int b_pxg = lane >> 4, b_khalf = (lane >> 3) & 1, b_row = lane & 7;
    int boff[2];
    #pragma unroll
    for (int jp = 0; jp < 2; jp++) {
        int p = pxbase + jp * 16 + b_pxg * 8 + b_row;
        int rr = p >> 5, cc = p & 31;
        boff[jp] = (rr * 34 + cc) * IN_PITCH + b_khalf * 4;
    }

    // ---- main loop over 9 shifts ----
    for (int s = 0; s < 9; s++) {
        int buf = s & 1;
        asm volatile("cp.async.wait_group 0;" ::: "memory");
        __syncthreads();
        if (s < 8) issueW(s + 1, buf ^ 1);
        int ky = s / 3, kx = s - 3 * ky;
        int soff = (ky * 34 + kx) * IN_PITCH;
        uint32_t whB = sbase + (WOFF + buf * WPLANE) * 4;
        uint32_t ihB = sbase + soff * 4;
        #pragma unroll
        for (int q = 0; q < 4; q++) {
            uint32_t ah[2][4], bh[2][4];
            #pragma unroll
            for (int mt = 0; mt < 2; mt++)
                ldsm4(ah[mt][0], ah[mt][1], ah[mt][2], ah[mt][3],
                      whB + (aoff[mt] + q * 8) * 4);
            #pragma unroll
            for (int jp = 0; jp < 2; jp++)
                ldsm4(bh[jp][0], bh[jp][1], bh[jp][2], bh[jp][3],
                      ihB + (boff[jp] + q * 8) * 4);
            #pragma unroll
            for (int mt = 0; mt < 2; mt++)
                #pragma unroll
                for (int j = 0; j < 4; j++) {
                    int jp = j >> 1, hf = (j & 1) * 2;
                    mma_f16(acc[mt][j], ah[mt][0], ah[mt][1], ah[mt][2], ah[mt][3],
                            bh[jp][hf], bh[jp][hf + 1]);
                }
        }
    }

    // ---- epilogue: transpose through smem (fp32, pitch 68), then coalesced out ----
    float* smf = reinterpret_cast<float*>(sm);
    __syncthreads();
    {
        #pragma unroll
        for (int mt = 0; mt < 2; mt++) {
            int col = cobase + mt * 16 + (lane >> 2);
            #pragma unroll
            for (int j = 0; j < 4; j++) {
                int p0 = pxbase + j * 8 + (lane & 3) * 2;
                smf[p0 * 68 + col]            = acc[mt][j][0];
                smf[(p0 + 1) * 68 + col]      = acc[mt][j][1];
                smf[p0 * 68 + col + 8]        = acc[mt][j][2];
                smf[(p0 + 1) * 68 + col + 8]  = acc[mt][j][3];
            }
        }
    }
    __syncthreads();
    size_t obase = ((size_t)b * HW + g * 128) * 64;
    float4 gsum = make_float4(0.f, 0.f, 0.f, 0.f);
    for (int idx = t; idx < 2048; idx += 256) {          // 128 px * 16 chunks of 4 co
        int px = idx >> 4, ck = idx & 15;
        float4 v = *reinterpret_cast<const float4*>(smf + px * 68 + ck * 4);
        size_t go = obase + (size_t)px * 64 + ck * 4;
        if (res) {
            uint2 rr = *reinterpret_cast<const uint2*>(res + go);
            const __half2* r2p = reinterpret_cast<const __half2*>(&rr);
            float2 a0 = __half22float2(r2p[0]), a1 = __half22float2(r2p[1]);
            v.x += a0.x; v.y += a0.y; v.z += a1.x; v.w += a1.y;
        }
        v.x = fmaxf(v.x, 0.f); v.y = fmaxf(v.y, 0.f);
        v.z = fmaxf(v.z, 0.f); v.w = fmaxf(v.w, 0.f);
        if (gap) { gsum.x += v.x; gsum.y += v.y; gsum.z += v.z; gsum.w += v.w; }
        __half h[4];
        h[0] = __float2half(v.x); h[1] = __float2half(v.y);
        h[2] = __float2half(v.z); h[3] = __float2half(v.w);
        *reinterpret_cast<uint2*>(out + go) = *reinterpret_cast<uint2*>(h);
    }
    if (gap) {                                           // ck fixed = t&15 per thread
        int ch = (t & 15) * 4;
        atomicAdd(&gap[b * 64 + ch],     gsum.x);
        atomicAdd(&gap[b * 64 + ch + 1], gsum.y);
        atomicAdd(&gap[b * 64 + ch + 2], gsum.z);
        atomicAdd(&gap[b * 64 + ch + 3], gsum.w);
    }
}

// ---------------- resnet FC + masked merge into d_out ----------------
__global__ void fc_merge(const float* __restrict__ gap, const float* __restrict__ rfc,
                         const float* __restrict__ rfb, const int* __restrict__ flag,
                         float* out) {
    __shared__ float sg[64];
    int b = blockIdx.x, t = threadIdx.x;
    sg[t] = gap[b * 64 + t] * (1.0f / 1024.0f);
    __syncthreads();
    if (t < 10) {
        float a = rfb[t];
        #pragma unroll
        for (int k = 0; k < 64; k++) a = fmaf(sg[k], rfc[k * 10 + t], a);
        if (flag[b]) out[(size_t)b * 10 + t] = a;
    }
}

// ---------------- launcher ----------------
extern "C" void kernel_launch(void* const* d_in, const int* in_sizes, int n_in,
                              void* d_out, int out_size) {
    const float* x    = (const float*)d_in[0];
    const float* thr  = (const float*)d_in[1];
    const int*   lab  = (const int*)d_in[2];
    const float* lw1  = (const float*)d_in[3];
    const float* lb1  = (const float*)d_in[4];
    const float* lw2  = (const float*)d_in[5];
    const float* lb2  = (const float*)d_in[6];
    const float* lfc1 = (const float*)d_in[7];
    const float* lfb1 = (const float*)d_in[8];
    const float* lfc2 = (const float*)d_in[9];
    const float* lfb2 = (const float*)d_in[10];
    const float* lfc3 = (const float*)d_in[11];
    const float* lfb3 = (const float*)d_in[12];
    const float* rw0  = (const float*)d_in[13];
    const float* rb0  = (const float*)d_in[14];
    const float* rw1a = (const float*)d_in[15];
    const float* rb1a = (const float*)d_in[16];
    const float* rw1b = (const float*)d_in[17];
    const float* rb1b = (const float*)d_in[18];
    const float* rw2a = (const float*)d_in[19];
    const float* rb2a = (const float*)d_in[20];
    const float* rw2b = (const float*)d_in[21];
    const float* rb2b = (const float*)d_in[22];
    const float* rfc  = (const float*)d_in[23];
    const float* rfb  = (const float*)d_in[24];

    float* out  = (float*)d_out;
    float* conf = out + BATCH * 10;

    __half *H, *R, *W, *W0;
    float *gapb; int* flag;
    cudaGetSymbolAddress((void**)&H,    g_H);
    cudaGetSymbolAddress((void**)&R,    g_R);
    cudaGetSymbolAddress((void**)&W,    g_W);
    cudaGetSymbolAddress((void**)&W0,   g_W0);
    cudaGetSymbolAddress((void**)&gapb, g_gap);
    cudaGetSymbolAddress((void**)&flag, g_flag);

    cudaFuncSetAttribute(conv_mma, cudaFuncAttributeMaxDynamicSharedMemorySize, SMEM_BYTES);
    cudaFuncSetAttribute(conv0_mma, cudaFuncAttributeMaxDynamicSharedMemorySize,
                         C0_SMEM_BYTES);

    const int WL = 9 * 64 * 72;
    prep_w<<<(WL + 255) / 256, 256>>>(rw1a, W + 0 * WL);
    prep_w<<<(WL + 255) / 256, 256>>>(rw1b, W + 1 * WL);
    prep_w<<<(WL + 255) / 256, 256>>>(rw2a, W + 2 * WL);
    prep_w<<<(WL + 255) / 256, 256>>>(rw2b, W + 3 * WL);
    prep_w0<<<10, 256>>>(rw0, W0);

    zero_conf<<<1, 128>>>(conf);

    // LeNet branch (fp32 exact) + gap zero
    lenet_all<<<BATCH, 256>>>(x, lw1, lb1, lw2, lb2, lfc1, lfb1, lfc2, lfb2,
                              lfc3, lfb3, thr, lab, out, conf, flag, gapb);

    // ResNet branch (fp16 NHWC activations, tensor cores end-to-end)
    dim3 g0(BATCH, 4);
    conv0_mma<<<g0, 256, C0_SMEM_BYTES>>>(x, W0, rb0, H);
    dim3 g(BATCH, 8);
    conv_mma<<<g, 256, SMEM_BYTES>>>(H, W + 0 * WL, rb1a, nullptr, R, nullptr);
    conv_mma<<<g, 256, SMEM_BYTES>>>(R, W + 1 * WL, rb1b, H,       H, nullptr);
    conv_mma<<<g, 256, SMEM_BYTES>>>(H, W + 2 * WL, rb2a, nullptr, R, nullptr);
    conv_mma<<<g, 256, SMEM_BYTES>>>(R, W + 3 * WL, rb2b, H,       H, gapb);

    fc_merge<<<BATCH, 64>>>(gapb, rfc, rfb, flag, out);
}